// round 4
// baseline (speedup 1.0000x reference)
#include <cuda_runtime.h>
#include <math.h>

#define D_MODEL 2048
#define NH 16
#define HD 128
#define SEQ 2048
#define BATCH 4
#define ROWS (BATCH * SEQ)       // 8192
#define D_FF 8192
#define QKV_N (3 * D_MODEL)      // 6144

// -------- scratch (static device globals; no cudaMalloc allowed) --------
__device__ float g_h[(size_t)ROWS * D_MODEL];      // LN output (tf32-rounded)
__device__ float g_qkv[(size_t)ROWS * QKV_N];      // fused QKV
__device__ float g_attn[(size_t)ROWS * D_MODEL];   // attention out (tf32-rounded)
__device__ float g_mlp[(size_t)ROWS * D_FF];       // MLP hidden (tf32-rounded)
// tf32-rounded weights: Wqkv | Wo | W1 | W2
#define WQKV_OFF 0
#define WO_OFF   (3 * D_MODEL * D_MODEL)                    // 12582912
#define W1_OFF   (WO_OFF + D_MODEL * D_MODEL)               // 16777216
#define W2_OFF   (W1_OFF + D_FF * D_MODEL)                  // 33554432
#define WR_TOTAL (W2_OFF + D_MODEL * D_FF)                  // 50331648
__device__ float g_wr[(size_t)WR_TOTAL];

// ============================ common mma helpers ============================
__device__ __forceinline__ float tf32r(float f) {
    unsigned u;
    asm("cvt.rna.tf32.f32 %0, %1;" : "=r"(u) : "f"(f));
    return __uint_as_float(u);
}

__device__ __forceinline__ void mma_tf32(float* c,
    float a0, float a1, float a2, float a3, float b0, float b1)
{
    asm volatile(
        "mma.sync.aligned.m16n8k8.row.col.f32.tf32.tf32.f32 "
        "{%0,%1,%2,%3}, {%4,%5,%6,%7}, {%8,%9}, {%0,%1,%2,%3};"
        : "+f"(c[0]), "+f"(c[1]), "+f"(c[2]), "+f"(c[3])
        : "r"(__float_as_uint(a0)), "r"(__float_as_uint(a1)),
          "r"(__float_as_uint(a2)), "r"(__float_as_uint(a3)),
          "r"(__float_as_uint(b0)), "r"(__float_as_uint(b1)));
}

// ============================ weight tf32 pre-round ============================
__global__ void __launch_bounds__(256) round_tf32_kernel(
    const float4* __restrict__ src, float4* __restrict__ dst, int n4)
{
    int i = blockIdx.x * 256 + threadIdx.x;
    if (i < n4) {
        float4 v = src[i];
        v.x = tf32r(v.x); v.y = tf32r(v.y); v.z = tf32r(v.z); v.w = tf32r(v.w);
        dst[i] = v;
    }
}

// ============================ LayerNorm (tf32-rounded output) ============================
__global__ void __launch_bounds__(256) ln_kernel(
    const float* __restrict__ x, const float* __restrict__ g,
    const float* __restrict__ b, float* __restrict__ out)
{
    __shared__ float red[2][8];
    int row = blockIdx.x, tid = threadIdx.x;
    const float4* xr = (const float4*)(x + (size_t)row * D_MODEL);
    float4 v0 = xr[tid];
    float4 v1 = xr[tid + 256];
    float s  = v0.x + v0.y + v0.z + v0.w + v1.x + v1.y + v1.z + v1.w;
    float s2 = v0.x*v0.x + v0.y*v0.y + v0.z*v0.z + v0.w*v0.w
             + v1.x*v1.x + v1.y*v1.y + v1.z*v1.z + v1.w*v1.w;
    #pragma unroll
    for (int o = 16; o; o >>= 1) {
        s  += __shfl_xor_sync(0xffffffffu, s,  o);
        s2 += __shfl_xor_sync(0xffffffffu, s2, o);
    }
    if ((tid & 31) == 0) { red[0][tid >> 5] = s; red[1][tid >> 5] = s2; }
    __syncthreads();
    if (tid < 32) {
        float a = (tid < 8) ? red[0][tid] : 0.f;
        float c = (tid < 8) ? red[1][tid] : 0.f;
        #pragma unroll
        for (int o = 4; o; o >>= 1) {
            a += __shfl_xor_sync(0xffffffffu, a, o);
            c += __shfl_xor_sync(0xffffffffu, c, o);
        }
        if (tid == 0) { red[0][0] = a; red[1][0] = c; }
    }
    __syncthreads();
    float mean = red[0][0] * (1.f / D_MODEL);
    float var  = red[1][0] * (1.f / D_MODEL) - mean * mean;
    float rstd = rsqrtf(var + 1e-5f);

    const float4* gr = (const float4*)g;
    const float4* br = (const float4*)b;
    float4* orow = (float4*)(out + (size_t)row * D_MODEL);
    #pragma unroll
    for (int p = 0; p < 2; p++) {
        float4 v = p ? v1 : v0;
        float4 gw = gr[tid + p * 256];
        float4 bw = br[tid + p * 256];
        float4 o;
        o.x = tf32r((v.x - mean) * rstd * gw.x + bw.x);
        o.y = tf32r((v.y - mean) * rstd * gw.y + bw.y);
        o.z = tf32r((v.z - mean) * rstd * gw.z + bw.z);
        o.w = tf32r((v.w - mean) * rstd * gw.w + bw.w);
        orow[tid + p * 256] = o;
    }
}

// ============================ tf32 tensor-core GEMM ============================
// Operands are pre-rounded to tf32 -> staging is a raw copy, no cvt in loop.
#define GBM 128
#define GBN 128
#define GBK 32
#define GEMM_SMEM (4 * 128 * 32 * 4)   // 2 bufs x (A+B) = 65536 B

__device__ __forceinline__ float gelu_exact(float v) {
    return 0.5f * v * (1.0f + erff(v * 0.70710678118654752f));
}

// scatter one staged set of 4 float4 into permuted+swizzled smem (no cvt)
__device__ __forceinline__ void stage_tile(const float4* st, float* buf, int tid)
{
    #pragma unroll
    for (int p = 0; p < 4; p++) {
        int idx = tid + 256 * p;
        int row = idx >> 3, c4 = idx & 7;      // c4 = k/4
        const float* e = (const float*)&st[p];
        #pragma unroll
        for (int ei = 0; ei < 4; ei++) {       // k = 4*c4 + ei -> kk = ei*8 + c4
            int f4l = 2 * ei + (c4 >> 2);
            int word = row * 32 + (((f4l ^ (row & 7))) << 2) + (c4 & 3);
            buf[word] = e[ei];
        }
    }
}

template <int EPI>
__global__ void __launch_bounds__(256, 2) gemm_kernel(
    const float* __restrict__ A, const float* __restrict__ B,
    const float* __restrict__ bias, const float* __restrict__ res,
    float* __restrict__ C, int M, int N, int K)
{
    extern __shared__ float sm[];
    int tid = threadIdx.x;
    int bm = blockIdx.y, bn = blockIdx.x;
    int warp = tid >> 5, lane = tid & 31;
    int wm = warp >> 1, wn = warp & 1;
    int g = lane >> 2, c = lane & 3;

    int srow = tid >> 3, sc4 = tid & 7;
    const float* Abase = A + (size_t)(bm * GBM + srow) * K + sc4 * 4;
    const float* Bbase = B + (size_t)(bn * GBN + srow) * K + sc4 * 4;

    float acc[2][8][4];
    #pragma unroll
    for (int mt = 0; mt < 2; mt++)
        #pragma unroll
        for (int nt = 0; nt < 8; nt++)
            #pragma unroll
            for (int q = 0; q < 4; q++) acc[mt][nt][q] = 0.f;

    int kt = K / GBK;

    // prologue: tile 0
    {
        float4 stA[4], stB[4];
        #pragma unroll
        for (int p = 0; p < 4; p++) {
            stA[p] = *(const float4*)(Abase + (size_t)(32 * p) * K);
            stB[p] = *(const float4*)(Bbase + (size_t)(32 * p) * K);
        }
        stage_tile(stA, sm, tid);
        stage_tile(stB, sm + 8192, tid);
    }
    __syncthreads();

    for (int kb = 0; kb < kt; ++kb) {
        int cur = kb & 1;
        if (kb + 1 < kt) {
            // stage next tile into the other buffer (readers synced last iter)
            float4 stA[4], stB[4];
            #pragma unroll
            for (int p = 0; p < 4; p++) {
                stA[p] = *(const float4*)(Abase + (size_t)(32 * p) * K + (kb + 1) * GBK);
                stB[p] = *(const float4*)(Bbase + (size_t)(32 * p) * K + (kb + 1) * GBK);
            }
            stage_tile(stA, sm + (1 - cur) * 4096, tid);
            stage_tile(stB, sm + 8192 + (1 - cur) * 4096, tid);
        }
        const float* Abuf = sm + cur * 4096;
        const float* Bbuf = sm + 8192 + cur * 4096;

        // process k-tile in two halves to keep fragment registers low
        #pragma unroll
        for (int u = 0; u < 2; u++) {
            float fa[2][2][4];
            #pragma unroll
            for (int mt = 0; mt < 2; mt++)
                #pragma unroll
                for (int rr = 0; rr < 2; rr++) {
                    int r = wm * 32 + mt * 16 + rr * 8 + g;
                    int f4p = (2 * c + u) ^ (r & 7);
                    *(float4*)fa[mt][rr] = *(const float4*)(Abuf + r * 32 + f4p * 4);
                }
            float fb[8][4];
            #pragma unroll
            for (int nt = 0; nt < 8; nt++) {
                int r = wn * 64 + nt * 8 + g;
                int f4p = (2 * c + u) ^ (r & 7);
                *(float4*)fb[nt] = *(const float4*)(Bbuf + r * 32 + f4p * 4);
            }
            #pragma unroll
            for (int s2 = 0; s2 < 2; s2++)
                #pragma unroll
                for (int mt = 0; mt < 2; mt++)
                    #pragma unroll
                    for (int nt = 0; nt < 8; nt++)
                        mma_tf32(acc[mt][nt],
                            fa[mt][0][2*s2], fa[mt][1][2*s2],
                            fa[mt][0][2*s2+1], fa[mt][1][2*s2+1],
                            fb[nt][2*s2], fb[nt][2*s2+1]);
        }
        __syncthreads();
    }

    int row0g = bm * GBM + wm * 32;
    int col0g = bn * GBN + wn * 64;
    #pragma unroll
    for (int mt = 0; mt < 2; mt++)
        #pragma unroll
        for (int nt = 0; nt < 8; nt++)
            #pragma unroll
            for (int h2 = 0; h2 < 2; h2++) {
                int row = row0g + mt * 16 + h2 * 8 + g;
                int col = col0g + nt * 8 + 2 * c;
                float2 v;
                v.x = acc[mt][nt][2 * h2 + 0] + bias[col];
                v.y = acc[mt][nt][2 * h2 + 1] + bias[col + 1];
                size_t off = (size_t)row * N + col;
                if (EPI == 1) {
                    float2 r = *(const float2*)(res + off);
                    v.x += r.x; v.y += r.y;
                }
                if (EPI == 2) {
                    v.x = tf32r(gelu_exact(v.x));
                    v.y = tf32r(gelu_exact(v.y));
                }
                *(float2*)(C + off) = v;
            }
}

// ============================ tf32 tensor-core flash attention ============================
#define SQ_STR 132
#define SK_STR 132
#define SV_STR 136
#define SP_STR 68
#define ATT_SMEM ((128*SQ_STR + 64*SK_STR + 64*SV_STR + 128*SP_STR) * 4)
#define NEG_BIG (-1e30f)

__global__ void __launch_bounds__(256, 1) attn_kernel(
    const float* __restrict__ qkv, const float* __restrict__ slopes,
    float* __restrict__ out)
{
    extern __shared__ float sm[];
    float* Qs = sm;
    float* Ks = Qs + 128 * SQ_STR;
    float* Vs = Ks + 64 * SK_STR;
    float* Ps = Vs + 64 * SV_STR;

    int qi = blockIdx.x, h = blockIdx.y, b = blockIdx.z;
    int tid = threadIdx.x, warp = tid >> 5, lane = tid & 31;
    int g = lane >> 2, c = lane & 3;
    int q0 = qi * 128;
    float slope = slopes[h];
    const float scale = 0.08838834764831845f;

    const float* qbase = qkv + (size_t)(b * SEQ) * QKV_N + h * HD;
    const float* kbase = qbase + D_MODEL;
    const float* vbase = qbase + 2 * D_MODEL;

    for (int i = tid; i < 128 * 32; i += 256) {
        int r = i >> 5, f4 = i & 31;
        float4 v = *(const float4*)(qbase + (size_t)(q0 + r) * QKV_N + f4 * 4);
        float* d = &Qs[r * SQ_STR + f4 * 4];
        d[0] = tf32r(v.x * scale); d[1] = tf32r(v.y * scale);
        d[2] = tf32r(v.z * scale); d[3] = tf32r(v.w * scale);
    }

    float m0 = NEG_BIG, m1 = NEG_BIG, l0 = 0.f, l1 = 0.f;
    float oc[16][4];
    #pragma unroll
    for (int nt = 0; nt < 16; nt++)
        #pragma unroll
        for (int q = 0; q < 4; q++) oc[nt][q] = 0.f;

    int rowA = 16 * warp + g;
    int qr0 = q0 + rowA, qr1 = qr0 + 8;
    const float* qa0 = &Qs[rowA * SQ_STR];
    const float* qa1 = qa0 + 8 * SQ_STR;
    float* pw0 = &Ps[rowA * SP_STR];
    float* pw1 = pw0 + 8 * SP_STR;

    int ntiles = 2 * qi + 2;
    for (int jt = 0; jt < ntiles; jt++) {
        int j0 = jt * 64;
        __syncthreads();
        for (int i = tid; i < 64 * 32; i += 256) {
            int r = i >> 5, f4 = i & 31;
            float4 kv = *(const float4*)(kbase + (size_t)(j0 + r) * QKV_N + f4 * 4);
            float* kd = &Ks[r * SK_STR + f4 * 4];
            kd[0] = tf32r(kv.x); kd[1] = tf32r(kv.y);
            kd[2] = tf32r(kv.z); kd[3] = tf32r(kv.w);
            float4 vv = *(const float4*)(vbase + (size_t)(j0 + r) * QKV_N + f4 * 4);
            float* vd = &Vs[r * SV_STR + f4 * 4];
            vd[0] = tf32r(vv.x); vd[1] = tf32r(vv.y);
            vd[2] = tf32r(vv.z); vd[3] = tf32r(vv.w);
        }
        __syncthreads();

        float sc[8][4];
        #pragma unroll
        for (int nt = 0; nt < 8; nt++)
            #pragma unroll
            for (int q = 0; q < 4; q++) sc[nt][q] = 0.f;

        #pragma unroll 4
        for (int s = 0; s < 16; s++) {
            int k0 = 8 * s;
            float a0 = qa0[k0 + c];
            float a1 = qa1[k0 + c];
            float a2 = qa0[k0 + c + 4];
            float a3 = qa1[k0 + c + 4];
            #pragma unroll
            for (int nt = 0; nt < 8; nt++) {
                const float* kr = &Ks[(nt * 8 + g) * SK_STR + k0];
                mma_tf32(sc[nt], a0, a1, a2, a3, kr[c], kr[c + 4]);
            }
        }

        bool masked = (jt >= 2 * qi);
        float tm0 = NEG_BIG, tm1 = NEG_BIG;
        #pragma unroll
        for (int nt = 0; nt < 8; nt++) {
            #pragma unroll
            for (int j = 0; j < 2; j++) {
                int col = j0 + nt * 8 + 2 * c + j;
                float d0 = (float)(col - qr0);
                float d1 = (float)(col - qr1);
                float s0 = sc[nt][j]     + slope * d0;
                float s1 = sc[nt][2 + j] + slope * d1;
                if (masked) {
                    if (col > qr0) s0 = NEG_BIG;
                    if (col > qr1) s1 = NEG_BIG;
                }
                sc[nt][j] = s0; sc[nt][2 + j] = s1;
                tm0 = fmaxf(tm0, s0); tm1 = fmaxf(tm1, s1);
            }
        }
        #pragma unroll
        for (int o = 1; o < 4; o <<= 1) {
            tm0 = fmaxf(tm0, __shfl_xor_sync(0xffffffffu, tm0, o));
            tm1 = fmaxf(tm1, __shfl_xor_sync(0xffffffffu, tm1, o));
        }
        float mn0 = fmaxf(m0, tm0), mn1 = fmaxf(m1, tm1);
        float alpha0 = __expf(m0 - mn0), alpha1 = __expf(m1 - mn1);
        float rs0 = 0.f, rs1 = 0.f;
        #pragma unroll
        for (int nt = 0; nt < 8; nt++) {
            #pragma unroll
            for (int j = 0; j < 2; j++) {
                float p0 = __expf(sc[nt][j]     - mn0);
                float p1 = __expf(sc[nt][2 + j] - mn1);
                sc[nt][j] = p0; sc[nt][2 + j] = p1;
                rs0 += p0; rs1 += p1;
            }
        }
        #pragma unroll
        for (int o = 1; o < 4; o <<= 1) {
            rs0 += __shfl_xor_sync(0xffffffffu, rs0, o);
            rs1 += __shfl_xor_sync(0xffffffffu, rs1, o);
        }
        l0 = l0 * alpha0 + rs0;
        l1 = l1 * alpha1 + rs1;
        m0 = mn0; m1 = mn1;
        #pragma unroll
        for (int nt = 0; nt < 16; nt++) {
            oc[nt][0] *= alpha0; oc[nt][1] *= alpha0;
            oc[nt][2] *= alpha1; oc[nt][3] *= alpha1;
        }

        #pragma unroll
        for (int nt = 0; nt < 8; nt++) {
            float2 w0 = make_float2(tf32r(sc[nt][0]), tf32r(sc[nt][1]));
            float2 w1 = make_float2(tf32r(sc[nt][2]), tf32r(sc[nt][3]));
            *(float2*)&pw0[nt * 8 + 2 * c] = w0;
            *(float2*)&pw1[nt * 8 + 2 * c] = w1;
        }
        __syncwarp();

        #pragma unroll 2
        for (int s = 0; s < 8; s++) {
            int k0 = 8 * s;
            float a0 = pw0[k0 + c];
            float a1 = pw1[k0 + c];
            float a2 = pw0[k0 + c + 4];
            float a3 = pw1[k0 + c + 4];
            const float* v0r = &Vs[(k0 + c) * SV_STR + g];
            const float* v1r = &Vs[(k0 + c + 4) * SV_STR + g];
            #pragma unroll
            for (int nt = 0; nt < 16; nt++)
                mma_tf32(oc[nt], a0, a1, a2, a3, v0r[nt * 8], v1r[nt * 8]);
        }
    }

    // normalize + write out, tf32-rounded (feeds O-proj GEMM as A operand)
    float inv0 = 1.f / l0, inv1 = 1.f / l1;
    float* ob = out + (size_t)(b * SEQ + qr0) * D_MODEL + h * HD;
    float* ob1 = ob + 8 * D_MODEL;
    #pragma unroll
    for (int nt = 0; nt < 16; nt++) {
        *(float2*)&ob[nt * 8 + 2 * c]  =
            make_float2(tf32r(oc[nt][0] * inv0), tf32r(oc[nt][1] * inv0));
        *(float2*)&ob1[nt * 8 + 2 * c] =
            make_float2(tf32r(oc[nt][2] * inv1), tf32r(oc[nt][3] * inv1));
    }
}

// ============================ launch ============================
extern "C" void kernel_launch(void* const* d_in, const int* in_sizes, int n_in,
                              void* d_out, int out_size)
{
    const float* x      = (const float*)d_in[0];
    const float* ln1_w  = (const float*)d_in[1];
    const float* ln1_b  = (const float*)d_in[2];
    const float* Wqkv   = (const float*)d_in[3];
    const float* bqkv   = (const float*)d_in[4];
    const float* Wo     = (const float*)d_in[5];
    const float* bo     = (const float*)d_in[6];
    const float* ln2_w  = (const float*)d_in[7];
    const float* ln2_b  = (const float*)d_in[8];
    const float* W1     = (const float*)d_in[9];
    const float* b1     = (const float*)d_in[10];
    const float* W2     = (const float*)d_in[11];
    const float* b2     = (const float*)d_in[12];
    const float* slopes = (const float*)d_in[13];
    float* out = (float*)d_out;

    float *h, *qkv, *attn, *mlp, *wr;
    cudaGetSymbolAddress((void**)&h,    g_h);
    cudaGetSymbolAddress((void**)&qkv,  g_qkv);
    cudaGetSymbolAddress((void**)&attn, g_attn);
    cudaGetSymbolAddress((void**)&mlp,  g_mlp);
    cudaGetSymbolAddress((void**)&wr,   g_wr);

    cudaFuncSetAttribute(attn_kernel,
                         cudaFuncAttributeMaxDynamicSharedMemorySize, ATT_SMEM);
    cudaFuncSetAttribute(gemm_kernel<0>,
                         cudaFuncAttributeMaxDynamicSharedMemorySize, GEMM_SMEM);
    cudaFuncSetAttribute(gemm_kernel<1>,
                         cudaFuncAttributeMaxDynamicSharedMemorySize, GEMM_SMEM);
    cudaFuncSetAttribute(gemm_kernel<2>,
                         cudaFuncAttributeMaxDynamicSharedMemorySize, GEMM_SMEM);

    // 0. pre-round weights to tf32 (scratch)
    {
        int n4;
        n4 = 3 * D_MODEL * D_MODEL / 4;
        round_tf32_kernel<<<(n4 + 255) / 256, 256>>>((const float4*)Wqkv,
            (float4*)(wr + WQKV_OFF), n4);
        n4 = D_MODEL * D_MODEL / 4;
        round_tf32_kernel<<<(n4 + 255) / 256, 256>>>((const float4*)Wo,
            (float4*)(wr + WO_OFF), n4);
        n4 = D_FF * D_MODEL / 4;
        round_tf32_kernel<<<(n4 + 255) / 256, 256>>>((const float4*)W1,
            (float4*)(wr + W1_OFF), n4);
        n4 = D_MODEL * D_FF / 4;
        round_tf32_kernel<<<(n4 + 255) / 256, 256>>>((const float4*)W2,
            (float4*)(wr + W2_OFF), n4);
    }

    // 1. LN1 (tf32-rounded output)
    ln_kernel<<<ROWS, 256>>>(x, ln1_w, ln1_b, h);
    // 2. QKV GEMM
    gemm_kernel<0><<<dim3(QKV_N / GBN, ROWS / GBM), 256, GEMM_SMEM>>>(
        h, wr + WQKV_OFF, bqkv, nullptr, qkv, ROWS, QKV_N, D_MODEL);
    // 3. Flash attention with ALiBi (tensor cores)
    attn_kernel<<<dim3(SEQ / 128, NH, BATCH), 256, ATT_SMEM>>>(qkv, slopes, attn);
    // 4. O projection + residual (x)  -> d_out holds x1
    gemm_kernel<1><<<dim3(D_MODEL / GBN, ROWS / GBM), 256, GEMM_SMEM>>>(
        attn, wr + WO_OFF, bo, x, out, ROWS, D_MODEL, D_MODEL);
    // 5. LN2
    ln_kernel<<<ROWS, 256>>>(out, ln2_w, ln2_b, h);
    // 6. MLP up + GELU (tf32-rounded output)
    gemm_kernel<2><<<dim3(D_FF / GBN, ROWS / GBM), 256, GEMM_SMEM>>>(
        h, wr + W1_OFF, b1, nullptr, mlp, ROWS, D_FF, D_MODEL);
    // 7. MLP down + residual (x1 in d_out) -> d_out final
    gemm_kernel<1><<<dim3(D_MODEL / GBN, ROWS / GBM), 256, GEMM_SMEM>>>(
        mlp, wr + W2_OFF, b2, out, out, ROWS, D_MODEL, D_FF);
}

// round 6
// speedup vs baseline: 3.9220x; 3.9220x over previous
#include <cuda_runtime.h>
#include <cuda_fp16.h>
#include <math.h>

#define D_MODEL 2048
#define NH 16
#define HD 128
#define SEQ 2048
#define BATCH 4
#define ROWS (BATCH * SEQ)       // 8192
#define D_FF 8192
#define QKV_N (3 * D_MODEL)      // 6144

// -------- scratch (static device globals; no cudaMalloc allowed) --------
__device__ __half g_h[(size_t)ROWS * D_MODEL];     // LN output (half)
__device__ float  g_qkv[(size_t)ROWS * QKV_N];     // fused QKV (fp32, attn input)
__device__ __half g_attn[(size_t)ROWS * D_MODEL];  // attention out (half)
__device__ __half g_mlp[(size_t)ROWS * D_FF];      // MLP hidden (half)
// half weights: Wqkv | Wo | W1 | W2
#define WQKV_OFF 0
#define WO_OFF   (3 * D_MODEL * D_MODEL)
#define W1_OFF   (WO_OFF + D_MODEL * D_MODEL)
#define W2_OFF   (W1_OFF + D_FF * D_MODEL)
#define WR_TOTAL (W2_OFF + D_MODEL * D_FF)
__device__ __half g_wh[(size_t)WR_TOTAL];

// ============================ helpers ============================
__device__ __forceinline__ float tf32r(float f) {
    unsigned u;
    asm("cvt.rna.tf32.f32 %0, %1;" : "=r"(u) : "f"(f));
    return __uint_as_float(u);
}

__device__ __forceinline__ void mma_tf32(float* c,
    float a0, float a1, float a2, float a3, float b0, float b1)
{
    asm volatile(
        "mma.sync.aligned.m16n8k8.row.col.f32.tf32.tf32.f32 "
        "{%0,%1,%2,%3}, {%4,%5,%6,%7}, {%8,%9}, {%0,%1,%2,%3};"
        : "+f"(c[0]), "+f"(c[1]), "+f"(c[2]), "+f"(c[3])
        : "r"(__float_as_uint(a0)), "r"(__float_as_uint(a1)),
          "r"(__float_as_uint(a2)), "r"(__float_as_uint(a3)),
          "r"(__float_as_uint(b0)), "r"(__float_as_uint(b1)));
}

__device__ __forceinline__ void mma_f16(float* c,
    unsigned a0, unsigned a1, unsigned a2, unsigned a3,
    unsigned b0, unsigned b1)
{
    asm volatile(
        "mma.sync.aligned.m16n8k16.row.col.f32.f16.f16.f32 "
        "{%0,%1,%2,%3}, {%4,%5,%6,%7}, {%8,%9}, {%0,%1,%2,%3};"
        : "+f"(c[0]), "+f"(c[1]), "+f"(c[2]), "+f"(c[3])
        : "r"(a0), "r"(a1), "r"(a2), "r"(a3), "r"(b0), "r"(b1));
}

__device__ __forceinline__ void cp16(void* dst_sh, const void* src) {
    unsigned sa = (unsigned)__cvta_generic_to_shared(dst_sh);
    asm volatile("cp.async.cg.shared.global [%0], [%1], 16;" :: "r"(sa), "l"(src));
}
__device__ __forceinline__ void cp_commit() {
    asm volatile("cp.async.commit_group;");
}
template <int N>
__device__ __forceinline__ void cp_wait() {
    asm volatile("cp.async.wait_group %0;" :: "n"(N));
}

__device__ __forceinline__ float gelu_exact(float v) {
    return 0.5f * v * (1.0f + erff(v * 0.70710678118654752f));
}

__device__ __forceinline__ unsigned h2u(__half2 h) {
    unsigned u;
    *(__half2*)&u = h;
    return u;
}

// ============================ fp32 -> fp16 convert ============================
__global__ void __launch_bounds__(256) to_half_kernel(
    const float4* __restrict__ src, uint4* __restrict__ dst, int n8)
{
    int i = blockIdx.x * 256 + threadIdx.x;
    if (i < n8) {
        float4 v0 = src[2 * i], v1 = src[2 * i + 1];
        uint4 o;
        o.x = h2u(__floats2half2_rn(v0.x, v0.y));
        o.y = h2u(__floats2half2_rn(v0.z, v0.w));
        o.z = h2u(__floats2half2_rn(v1.x, v1.y));
        o.w = h2u(__floats2half2_rn(v1.z, v1.w));
        dst[i] = o;
    }
}

// ============================ LayerNorm (half output) ============================
__global__ void __launch_bounds__(256) ln_kernel(
    const float* __restrict__ x, const float* __restrict__ g,
    const float* __restrict__ b, __half* __restrict__ out)
{
    __shared__ float red[2][8];
    int row = blockIdx.x, tid = threadIdx.x;
    const float4* xr = (const float4*)(x + (size_t)row * D_MODEL);
    float4 v0 = xr[tid];
    float4 v1 = xr[tid + 256];
    float s  = v0.x + v0.y + v0.z + v0.w + v1.x + v1.y + v1.z + v1.w;
    float s2 = v0.x*v0.x + v0.y*v0.y + v0.z*v0.z + v0.w*v0.w
             + v1.x*v1.x + v1.y*v1.y + v1.z*v1.z + v1.w*v1.w;
    #pragma unroll
    for (int o = 16; o; o >>= 1) {
        s  += __shfl_xor_sync(0xffffffffu, s,  o);
        s2 += __shfl_xor_sync(0xffffffffu, s2, o);
    }
    if ((tid & 31) == 0) { red[0][tid >> 5] = s; red[1][tid >> 5] = s2; }
    __syncthreads();
    if (tid < 32) {
        float a = (tid < 8) ? red[0][tid] : 0.f;
        float c = (tid < 8) ? red[1][tid] : 0.f;
        #pragma unroll
        for (int o = 4; o; o >>= 1) {
            a += __shfl_xor_sync(0xffffffffu, a, o);
            c += __shfl_xor_sync(0xffffffffu, c, o);
        }
        if (tid == 0) { red[0][0] = a; red[1][0] = c; }
    }
    __syncthreads();
    float mean = red[0][0] * (1.f / D_MODEL);
    float var  = red[1][0] * (1.f / D_MODEL) - mean * mean;
    float rstd = rsqrtf(var + 1e-5f);

    const float4* gr = (const float4*)g;
    const float4* br = (const float4*)b;
    __half2* orow = (__half2*)(out + (size_t)row * D_MODEL);
    #pragma unroll
    for (int p = 0; p < 2; p++) {
        float4 v = p ? v1 : v0;
        float4 gw = gr[tid + p * 256];
        float4 bw = br[tid + p * 256];
        orow[2 * (tid + p * 256) + 0] = __floats2half2_rn(
            (v.x - mean) * rstd * gw.x + bw.x,
            (v.y - mean) * rstd * gw.y + bw.y);
        orow[2 * (tid + p * 256) + 1] = __floats2half2_rn(
            (v.z - mean) * rstd * gw.z + bw.z,
            (v.w - mean) * rstd * gw.w + bw.w);
    }
}

// ============================ fp16 tensor-core GEMM + cp.async ============================
// C[M,N] = A[M,K] @ B[N,K]^T + bias[N]  (+ epilogue)
// EPI: 0 = bias -> fp32 out; 1 = bias + fp32 residual -> fp32 out;
//      2 = bias + exact GELU -> half out
// CTA 128x128xBK64, 8 warps 4(m)x2(n), warp tile 32x64 as 2x8 m16n8 mmas.
// smem rows = 64 halfs (128B) with 16B-chunk XOR swizzle (c8 ^ (row&7)):
// conflict-free LDGSTS and conflict-free scalar .b32 fragment LDS.
#define GBM 128
#define GBN 128
#define GBK 64
#define TILE_H (128 * 64)                 // halfs per operand tile
#define GEMM_SMEM (4 * TILE_H * 2)        // 2 bufs x (A+B), bytes = 65536

template <int EPI>
__global__ void __launch_bounds__(256, 2) gemm_kernel(
    const __half* __restrict__ A, const __half* __restrict__ B,
    const float* __restrict__ bias, const float* __restrict__ res,
    void* __restrict__ Cv, int M, int N, int K)
{
    extern __shared__ __half smh[];
    int tid = threadIdx.x;
    int bm = blockIdx.y, bn = blockIdx.x;
    int warp = tid >> 5, lane = tid & 31;
    int wm = warp >> 1, wn = warp & 1;
    int g = lane >> 2, c = lane & 3;

    // staging descriptors: 4 A-chunks + 4 B-chunks of 16B per thread per ktile
    const __half* Asrc[4]; const __half* Bsrc[4]; int sdst[4];
    #pragma unroll
    for (int p = 0; p < 4; p++) {
        int cid = tid + 256 * p;
        int row = cid >> 3, c8 = cid & 7;
        Asrc[p] = A + (size_t)(bm * GBM + row) * K + c8 * 8;
        Bsrc[p] = B + (size_t)(bn * GBN + row) * K + c8 * 8;
        sdst[p] = row * 64 + ((c8 ^ (row & 7)) << 3);
    }

    float acc[2][8][4];
    #pragma unroll
    for (int mt = 0; mt < 2; mt++)
        #pragma unroll
        for (int nt = 0; nt < 8; nt++)
            #pragma unroll
            for (int q = 0; q < 4; q++) acc[mt][nt][q] = 0.f;

    int kt = K / GBK;

    // fragment base offsets (halfs); k-position: chunk (ks ^ g), pair c within chunk
    int aoff = (wm * 32 + g) * 64 + 2 * c;     // + mt*1024, +512 for row+8
    int boff = (wn * 64 + g) * 64 + 2 * c;     // + nt*512

    // prologue: stage ktile 0 into buffer 0
    #pragma unroll
    for (int p = 0; p < 4; p++) {
        cp16(smh + sdst[p], Asrc[p]);
        cp16(smh + 2 * TILE_H + sdst[p], Bsrc[p]);
    }
    cp_commit();

    for (int kb = 0; kb < kt; ++kb) {
        int cur = kb & 1;
        if (kb + 1 < kt) {
            int nxt = 1 - cur;
            #pragma unroll
            for (int p = 0; p < 4; p++) {
                cp16(smh + nxt * TILE_H + sdst[p], Asrc[p] + (kb + 1) * GBK);
                cp16(smh + 2 * TILE_H + nxt * TILE_H + sdst[p], Bsrc[p] + (kb + 1) * GBK);
            }
            cp_commit();
            cp_wait<1>();
        } else {
            cp_wait<0>();
        }
        __syncthreads();

        const __half* Abuf = smh + cur * TILE_H;
        const __half* Bbuf = smh + 2 * TILE_H + cur * TILE_H;

        #pragma unroll
        for (int ks = 0; ks < 4; ks++) {
            int q0 = ((2 * ks) ^ g) << 3;       // k chunk for k-half 0
            int q1 = ((2 * ks + 1) ^ g) << 3;   // k chunk for k-half 1
            unsigned fa[2][4];
            #pragma unroll
            for (int mt = 0; mt < 2; mt++) {
                int base = aoff + mt * 1024;
                fa[mt][0] = *(const unsigned*)(Abuf + base + q0);
                fa[mt][1] = *(const unsigned*)(Abuf + base + 512 + q0);
                fa[mt][2] = *(const unsigned*)(Abuf + base + q1);
                fa[mt][3] = *(const unsigned*)(Abuf + base + 512 + q1);
            }
            unsigned fb[8][2];
            #pragma unroll
            for (int nt = 0; nt < 8; nt++) {
                int base = boff + nt * 512;
                fb[nt][0] = *(const unsigned*)(Bbuf + base + q0);
                fb[nt][1] = *(const unsigned*)(Bbuf + base + q1);
            }
            #pragma unroll
            for (int mt = 0; mt < 2; mt++)
                #pragma unroll
                for (int nt = 0; nt < 8; nt++)
                    mma_f16(acc[mt][nt], fa[mt][0], fa[mt][1], fa[mt][2], fa[mt][3],
                            fb[nt][0], fb[nt][1]);
        }
        __syncthreads();
    }

    // epilogue
    int row0g = bm * GBM + wm * 32;
    int col0g = bn * GBN + wn * 64;
    #pragma unroll
    for (int mt = 0; mt < 2; mt++)
        #pragma unroll
        for (int nt = 0; nt < 8; nt++)
            #pragma unroll
            for (int h2 = 0; h2 < 2; h2++) {
                int row = row0g + mt * 16 + h2 * 8 + g;
                int col = col0g + nt * 8 + 2 * c;
                float vx = acc[mt][nt][2 * h2 + 0] + bias[col];
                float vy = acc[mt][nt][2 * h2 + 1] + bias[col + 1];
                size_t off = (size_t)row * N + col;
                if (EPI == 2) {
                    __half* Ch = (__half*)Cv;
                    *(__half2*)(Ch + off) =
                        __floats2half2_rn(gelu_exact(vx), gelu_exact(vy));
                } else {
                    float* Cf = (float*)Cv;
                    if (EPI == 1) {
                        float2 r = *(const float2*)(res + off);
                        vx += r.x; vy += r.y;
                    }
                    *(float2*)(Cf + off) = make_float2(vx, vy);
                }
            }
}

// ============================ tf32 tensor-core flash attention ============================
#define SQ_STR 132
#define SK_STR 132
#define SV_STR 136
#define SP_STR 68
#define ATT_SMEM ((128*SQ_STR + 64*SK_STR + 64*SV_STR + 128*SP_STR) * 4)
#define NEG_BIG (-1e30f)

__global__ void __launch_bounds__(256, 1) attn_kernel(
    const float* __restrict__ qkv, const float* __restrict__ slopes,
    __half* __restrict__ out)
{
    extern __shared__ float sm[];
    float* Qs = sm;
    float* Ks = Qs + 128 * SQ_STR;
    float* Vs = Ks + 64 * SK_STR;
    float* Ps = Vs + 64 * SV_STR;

    int qi = blockIdx.x, h = blockIdx.y, b = blockIdx.z;
    int tid = threadIdx.x, warp = tid >> 5, lane = tid & 31;
    int g = lane >> 2, c = lane & 3;
    int q0 = qi * 128;
    float slope = slopes[h];
    const float scale = 0.08838834764831845f;

    const float* qbase = qkv + (size_t)(b * SEQ) * QKV_N + h * HD;
    const float* kbase = qbase + D_MODEL;
    const float* vbase = qbase + 2 * D_MODEL;

    for (int i = tid; i < 128 * 32; i += 256) {
        int r = i >> 5, f4 = i & 31;
        float4 v = *(const float4*)(qbase + (size_t)(q0 + r) * QKV_N + f4 * 4);
        float* d = &Qs[r * SQ_STR + f4 * 4];
        d[0] = tf32r(v.x * scale); d[1] = tf32r(v.y * scale);
        d[2] = tf32r(v.z * scale); d[3] = tf32r(v.w * scale);
    }

    float m0 = NEG_BIG, m1 = NEG_BIG, l0 = 0.f, l1 = 0.f;
    float oc[16][4];
    #pragma unroll
    for (int nt = 0; nt < 16; nt++)
        #pragma unroll
        for (int q = 0; q < 4; q++) oc[nt][q] = 0.f;

    int rowA = 16 * warp + g;
    int qr0 = q0 + rowA, qr1 = qr0 + 8;
    const float* qa0 = &Qs[rowA * SQ_STR];
    const float* qa1 = qa0 + 8 * SQ_STR;
    float* pw0 = &Ps[rowA * SP_STR];
    float* pw1 = pw0 + 8 * SP_STR;

    int ntiles = 2 * qi + 2;
    for (int jt = 0; jt < ntiles; jt++) {
        int j0 = jt * 64;
        __syncthreads();
        for (int i = tid; i < 64 * 32; i += 256) {
            int r = i >> 5, f4 = i & 31;
            float4 kv = *(const float4*)(kbase + (size_t)(j0 + r) * QKV_N + f4 * 4);
            float* kd = &Ks[r * SK_STR + f4 * 4];
            kd[0] = tf32r(kv.x); kd[1] = tf32r(kv.y);
            kd[2] = tf32r(kv.z); kd[3] = tf32r(kv.w);
            float4 vv = *(const float4*)(vbase + (size_t)(j0 + r) * QKV_N + f4 * 4);
            float* vd = &Vs[r * SV_STR + f4 * 4];
            vd[0] = tf32r(vv.x); vd[1] = tf32r(vv.y);
            vd[2] = tf32r(vv.z); vd[3] = tf32r(vv.w);
        }
        __syncthreads();

        float sc[8][4];
        #pragma unroll
        for (int nt = 0; nt < 8; nt++)
            #pragma unroll
            for (int q = 0; q < 4; q++) sc[nt][q] = 0.f;

        #pragma unroll 4
        for (int s = 0; s < 16; s++) {
            int k0 = 8 * s;
            float a0 = qa0[k0 + c];
            float a1 = qa1[k0 + c];
            float a2 = qa0[k0 + c + 4];
            float a3 = qa1[k0 + c + 4];
            #pragma unroll
            for (int nt = 0; nt < 8; nt++) {
                const float* kr = &Ks[(nt * 8 + g) * SK_STR + k0];
                mma_tf32(sc[nt], a0, a1, a2, a3, kr[c], kr[c + 4]);
            }
        }

        bool masked = (jt >= 2 * qi);
        float tm0 = NEG_BIG, tm1 = NEG_BIG;
        #pragma unroll
        for (int nt = 0; nt < 8; nt++) {
            #pragma unroll
            for (int j = 0; j < 2; j++) {
                int col = j0 + nt * 8 + 2 * c + j;
                float d0 = (float)(col - qr0);
                float d1 = (float)(col - qr1);
                float s0 = sc[nt][j]     + slope * d0;
                float s1 = sc[nt][2 + j] + slope * d1;
                if (masked) {
                    if (col > qr0) s0 = NEG_BIG;
                    if (col > qr1) s1 = NEG_BIG;
                }
                sc[nt][j] = s0; sc[nt][2 + j] = s1;
                tm0 = fmaxf(tm0, s0); tm1 = fmaxf(tm1, s1);
            }
        }
        #pragma unroll
        for (int o = 1; o < 4; o <<= 1) {
            tm0 = fmaxf(tm0, __shfl_xor_sync(0xffffffffu, tm0, o));
            tm1 = fmaxf(tm1, __shfl_xor_sync(0xffffffffu, tm1, o));
        }
        float mn0 = fmaxf(m0, tm0), mn1 = fmaxf(m1, tm1);
        float alpha0 = __expf(m0 - mn0), alpha1 = __expf(m1 - mn1);
        float rs0 = 0.f, rs1 = 0.f;
        #pragma unroll
        for (int nt = 0; nt < 8; nt++) {
            #pragma unroll
            for (int j = 0; j < 2; j++) {
                float p0 = __expf(sc[nt][j]     - mn0);
                float p1 = __expf(sc[nt][2 + j] - mn1);
                sc[nt][j] = p0; sc[nt][2 + j] = p1;
                rs0 += p0; rs1 += p1;
            }
        }
        #pragma unroll
        for (int o = 1; o < 4; o <<= 1) {
            rs0 += __shfl_xor_sync(0xffffffffu, rs0, o);
            rs1 += __shfl_xor_sync(0xffffffffu, rs1, o);
        }
        l0 = l0 * alpha0 + rs0;
        l1 = l1 * alpha1 + rs1;
        m0 = mn0; m1 = mn1;
        #pragma unroll
        for (int nt = 0; nt < 16; nt++) {
            oc[nt][0] *= alpha0; oc[nt][1] *= alpha0;
            oc[nt][2] *= alpha1; oc[nt][3] *= alpha1;
        }

        #pragma unroll
        for (int nt = 0; nt < 8; nt++) {
            float2 w0 = make_float2(tf32r(sc[nt][0]), tf32r(sc[nt][1]));
            float2 w1 = make_float2(tf32r(sc[nt][2]), tf32r(sc[nt][3]));
            *(float2*)&pw0[nt * 8 + 2 * c] = w0;
            *(float2*)&pw1[nt * 8 + 2 * c] = w1;
        }
        __syncwarp();

        #pragma unroll 2
        for (int s = 0; s < 8; s++) {
            int k0 = 8 * s;
            float a0 = pw0[k0 + c];
            float a1 = pw1[k0 + c];
            float a2 = pw0[k0 + c + 4];
            float a3 = pw1[k0 + c + 4];
            const float* v0r = &Vs[(k0 + c) * SV_STR + g];
            const float* v1r = &Vs[(k0 + c + 4) * SV_STR + g];
            #pragma unroll
            for (int nt = 0; nt < 16; nt++)
                mma_tf32(oc[nt], a0, a1, a2, a3, v0r[nt * 8], v1r[nt * 8]);
        }
    }

    // normalize + write out as half (feeds O-proj GEMM)
    float inv0 = 1.f / l0, inv1 = 1.f / l1;
    __half* ob  = out + (size_t)(b * SEQ + qr0) * D_MODEL + h * HD;
    __half* ob1 = ob + 8 * D_MODEL;
    #pragma unroll
    for (int nt = 0; nt < 16; nt++) {
        *(__half2*)&ob[nt * 8 + 2 * c] =
            __floats2half2_rn(oc[nt][0] * inv0, oc[nt][1] * inv0);
        *(__half2*)&ob1[nt * 8 + 2 * c] =
            __floats2half2_rn(oc[nt][2] * inv1, oc[nt][3] * inv1);
    }
}

// ============================ launch ============================
extern "C" void kernel_launch(void* const* d_in, const int* in_sizes, int n_in,
                              void* d_out, int out_size)
{
    const float* x      = (const float*)d_in[0];
    const float* ln1_w  = (const float*)d_in[1];
    const float* ln1_b  = (const float*)d_in[2];
    const float* Wqkv   = (const float*)d_in[3];
    const float* bqkv   = (const float*)d_in[4];
    const float* Wo     = (const float*)d_in[5];
    const float* bo     = (const float*)d_in[6];
    const float* ln2_w  = (const float*)d_in[7];
    const float* ln2_b  = (const float*)d_in[8];
    const float* W1     = (const float*)d_in[9];
    const float* b1     = (const float*)d_in[10];
    const float* W2     = (const float*)d_in[11];
    const float* b2     = (const float*)d_in[12];
    const float* slopes = (const float*)d_in[13];
    float* out = (float*)d_out;

    __half *h, *attn, *mlp, *wh;
    float *qkv;
    cudaGetSymbolAddress((void**)&h,    g_h);
    cudaGetSymbolAddress((void**)&qkv,  g_qkv);
    cudaGetSymbolAddress((void**)&attn, g_attn);
    cudaGetSymbolAddress((void**)&mlp,  g_mlp);
    cudaGetSymbolAddress((void**)&wh,   g_wh);

    cudaFuncSetAttribute(attn_kernel,
                         cudaFuncAttributeMaxDynamicSharedMemorySize, ATT_SMEM);
    cudaFuncSetAttribute(gemm_kernel<0>,
                         cudaFuncAttributeMaxDynamicSharedMemorySize, GEMM_SMEM);
    cudaFuncSetAttribute(gemm_kernel<1>,
                         cudaFuncAttributeMaxDynamicSharedMemorySize, GEMM_SMEM);
    cudaFuncSetAttribute(gemm_kernel<2>,
                         cudaFuncAttributeMaxDynamicSharedMemorySize, GEMM_SMEM);

    // 0. convert weights to half
    {
        int n8;
        n8 = 3 * D_MODEL * D_MODEL / 8;
        to_half_kernel<<<(n8 + 255) / 256, 256>>>((const float4*)Wqkv,
            (uint4*)(wh + WQKV_OFF), n8);
        n8 = D_MODEL * D_MODEL / 8;
        to_half_kernel<<<(n8 + 255) / 256, 256>>>((const float4*)Wo,
            (uint4*)(wh + WO_OFF), n8);
        n8 = D_FF * D_MODEL / 8;
        to_half_kernel<<<(n8 + 255) / 256, 256>>>((const float4*)W1,
            (uint4*)(wh + W1_OFF), n8);
        n8 = D_MODEL * D_FF / 8;
        to_half_kernel<<<(n8 + 255) / 256, 256>>>((const float4*)W2,
            (uint4*)(wh + W2_OFF), n8);
    }

    // 1. LN1 -> half
    ln_kernel<<<ROWS, 256>>>(x, ln1_w, ln1_b, h);
    // 2. QKV GEMM (half x half -> fp32)
    gemm_kernel<0><<<dim3(QKV_N / GBN, ROWS / GBM), 256, GEMM_SMEM>>>(
        h, wh + WQKV_OFF, bqkv, nullptr, qkv, ROWS, QKV_N, D_MODEL);
    // 3. Flash attention with ALiBi (tf32 TC) -> half
    attn_kernel<<<dim3(SEQ / 128, NH, BATCH), 256, ATT_SMEM>>>(qkv, slopes, attn);
    // 4. O projection + residual (x) -> d_out fp32
    gemm_kernel<1><<<dim3(D_MODEL / GBN, ROWS / GBM), 256, GEMM_SMEM>>>(
        attn, wh + WO_OFF, bo, x, out, ROWS, D_MODEL, D_MODEL);
    // 5. LN2 -> half
    ln_kernel<<<ROWS, 256>>>(out, ln2_w, ln2_b, h);
    // 6. MLP up + GELU -> half
    gemm_kernel<2><<<dim3(D_FF / GBN, ROWS / GBM), 256, GEMM_SMEM>>>(
        h, wh + W1_OFF, b1, nullptr, mlp, ROWS, D_FF, D_MODEL);
    // 7. MLP down + residual (x1 in d_out) -> d_out fp32 final
    gemm_kernel<1><<<dim3(D_MODEL / GBN, ROWS / GBM), 256, GEMM_SMEM>>>(
        mlp, wh + W2_OFF, b2, out, out, ROWS, D_MODEL, D_FF);
}

// round 8
// speedup vs baseline: 4.2162x; 1.0750x over previous
#include <cuda_runtime.h>
#include <cuda_fp16.h>
#include <math.h>

#define D_MODEL 2048
#define NH 16
#define HD 128
#define SEQ 2048
#define BATCH 4
#define ROWS (BATCH * SEQ)       // 8192
#define D_FF 8192
#define QKV_N (3 * D_MODEL)      // 6144

// -------- scratch (static device globals; no cudaMalloc allowed) --------
__device__ __half g_h[(size_t)ROWS * D_MODEL];     // LN output (half)
__device__ float  g_qkv[(size_t)ROWS * QKV_N];     // fused QKV (fp32, attn input)
__device__ __half g_attn[(size_t)ROWS * D_MODEL];  // attention out (half)
__device__ __half g_mlp[(size_t)ROWS * D_FF];      // MLP hidden (half)
// half weights: Wqkv | Wo | W1 | W2
#define WQKV_OFF 0
#define WO_OFF   (3 * D_MODEL * D_MODEL)
#define W1_OFF   (WO_OFF + D_MODEL * D_MODEL)
#define W2_OFF   (W1_OFF + D_FF * D_MODEL)
#define WR_TOTAL (W2_OFF + D_MODEL * D_FF)
__device__ __half g_wh[(size_t)WR_TOTAL];

// ============================ helpers ============================
__device__ __forceinline__ float tf32r(float f) {
    unsigned u;
    asm("cvt.rna.tf32.f32 %0, %1;" : "=r"(u) : "f"(f));
    return __uint_as_float(u);
}

__device__ __forceinline__ void mma_tf32(float* c,
    float a0, float a1, float a2, float a3, float b0, float b1)
{
    asm volatile(
        "mma.sync.aligned.m16n8k8.row.col.f32.tf32.tf32.f32 "
        "{%0,%1,%2,%3}, {%4,%5,%6,%7}, {%8,%9}, {%0,%1,%2,%3};"
        : "+f"(c[0]), "+f"(c[1]), "+f"(c[2]), "+f"(c[3])
        : "r"(__float_as_uint(a0)), "r"(__float_as_uint(a1)),
          "r"(__float_as_uint(a2)), "r"(__float_as_uint(a3)),
          "r"(__float_as_uint(b0)), "r"(__float_as_uint(b1)));
}

__device__ __forceinline__ void mma_f16(float* c,
    unsigned a0, unsigned a1, unsigned a2, unsigned a3,
    unsigned b0, unsigned b1)
{
    asm volatile(
        "mma.sync.aligned.m16n8k16.row.col.f32.f16.f16.f32 "
        "{%0,%1,%2,%3}, {%4,%5,%6,%7}, {%8,%9}, {%0,%1,%2,%3};"
        : "+f"(c[0]), "+f"(c[1]), "+f"(c[2]), "+f"(c[3])
        : "r"(a0), "r"(a1), "r"(a2), "r"(a3), "r"(b0), "r"(b1));
}

__device__ __forceinline__ void ldsm4(unsigned* r, unsigned addr) {
    asm volatile(
        "ldmatrix.sync.aligned.m8n8.x4.shared.b16 {%0,%1,%2,%3}, [%4];"
        : "=r"(r[0]), "=r"(r[1]), "=r"(r[2]), "=r"(r[3]) : "r"(addr));
}

__device__ __forceinline__ void cp16(void* dst_sh, const void* src) {
    unsigned sa = (unsigned)__cvta_generic_to_shared(dst_sh);
    asm volatile("cp.async.cg.shared.global [%0], [%1], 16;" :: "r"(sa), "l"(src));
}
__device__ __forceinline__ void cp_commit() {
    asm volatile("cp.async.commit_group;");
}
template <int N>
__device__ __forceinline__ void cp_wait() {
    asm volatile("cp.async.wait_group %0;" :: "n"(N));
}

__device__ __forceinline__ float gelu_exact(float v) {
    return 0.5f * v * (1.0f + erff(v * 0.70710678118654752f));
}

__device__ __forceinline__ unsigned h2u(__half2 h) {
    unsigned u;
    *(__half2*)&u = h;
    return u;
}

// ============================ fp32 -> fp16 convert ============================
__global__ void __launch_bounds__(256) to_half_kernel(
    const float4* __restrict__ src, uint4* __restrict__ dst, int n8)
{
    int i = blockIdx.x * 256 + threadIdx.x;
    if (i < n8) {
        float4 v0 = src[2 * i], v1 = src[2 * i + 1];
        uint4 o;
        o.x = h2u(__floats2half2_rn(v0.x, v0.y));
        o.y = h2u(__floats2half2_rn(v0.z, v0.w));
        o.z = h2u(__floats2half2_rn(v1.x, v1.y));
        o.w = h2u(__floats2half2_rn(v1.z, v1.w));
        dst[i] = o;
    }
}

// ============================ LayerNorm (half output) ============================
__global__ void __launch_bounds__(256) ln_kernel(
    const float* __restrict__ x, const float* __restrict__ g,
    const float* __restrict__ b, __half* __restrict__ out)
{
    __shared__ float red[2][8];
    int row = blockIdx.x, tid = threadIdx.x;
    const float4* xr = (const float4*)(x + (size_t)row * D_MODEL);
    float4 v0 = xr[tid];
    float4 v1 = xr[tid + 256];
    float s  = v0.x + v0.y + v0.z + v0.w + v1.x + v1.y + v1.z + v1.w;
    float s2 = v0.x*v0.x + v0.y*v0.y + v0.z*v0.z + v0.w*v0.w
             + v1.x*v1.x + v1.y*v1.y + v1.z*v1.z + v1.w*v1.w;
    #pragma unroll
    for (int o = 16; o; o >>= 1) {
        s  += __shfl_xor_sync(0xffffffffu, s,  o);
        s2 += __shfl_xor_sync(0xffffffffu, s2, o);
    }
    if ((tid & 31) == 0) { red[0][tid >> 5] = s; red[1][tid >> 5] = s2; }
    __syncthreads();
    if (tid < 32) {
        float a = (tid < 8) ? red[0][tid] : 0.f;
        float c = (tid < 8) ? red[1][tid] : 0.f;
        #pragma unroll
        for (int o = 4; o; o >>= 1) {
            a += __shfl_xor_sync(0xffffffffu, a, o);
            c += __shfl_xor_sync(0xffffffffu, c, o);
        }
        if (tid == 0) { red[0][0] = a; red[1][0] = c; }
    }
    __syncthreads();
    float mean = red[0][0] * (1.f / D_MODEL);
    float var  = red[1][0] * (1.f / D_MODEL) - mean * mean;
    float rstd = rsqrtf(var + 1e-5f);

    const float4* gr = (const float4*)g;
    const float4* br = (const float4*)b;
    __half2* orow = (__half2*)(out + (size_t)row * D_MODEL);
    #pragma unroll
    for (int p = 0; p < 2; p++) {
        float4 v = p ? v1 : v0;
        float4 gw = gr[tid + p * 256];
        float4 bw = br[tid + p * 256];
        orow[2 * (tid + p * 256) + 0] = __floats2half2_rn(
            (v.x - mean) * rstd * gw.x + bw.x,
            (v.y - mean) * rstd * gw.y + bw.y);
        orow[2 * (tid + p * 256) + 1] = __floats2half2_rn(
            (v.z - mean) * rstd * gw.z + bw.z,
            (v.w - mean) * rstd * gw.w + bw.w);
    }
}

// ============================ fp16 mma GEMM: cp.async 3-stage + ldmatrix ============================
// C[M,N] = A[M,K] @ B[N,K]^T + bias[N]  (+ epilogue)
// EPI: 0 = bias -> fp32; 1 = bias + fp32 residual -> fp32; 2 = bias + GELU -> half
// CTA 128x128xBK64, 8 warps 4(m)x2(n), warp tile 32x64 as 2x8 m16n8k16 mmas.
// smem rows = 64 halfs (128B) with 16B-chunk XOR swizzle (c8 ^ (row&7)):
// conflict-free LDGSTS and conflict-free ldmatrix.x4 fragment loads.
#define GBM 128
#define GBN 128
#define GBK 64
#define TILE_H (128 * 64)                 // halfs per operand tile (16 KB)
#define NSTAGE 3
#define STAGE_H (2 * TILE_H)              // A+B per stage (halfs)
#define GEMM_SMEM (NSTAGE * STAGE_H * 2)  // bytes = 98304

template <int EPI>
__global__ void __launch_bounds__(256, 2) gemm_kernel(
    const __half* __restrict__ A, const __half* __restrict__ B,
    const float* __restrict__ bias, const float* __restrict__ res,
    void* __restrict__ Cv, int M, int N, int K)
{
    extern __shared__ __half smh[];
    int tid = threadIdx.x;
    int bm = blockIdx.y, bn = blockIdx.x;
    int warp = tid >> 5, lane = tid & 31;
    int wm = warp >> 1, wn = warp & 1;
    int g = lane >> 2, c = lane & 3;

    // ---- staging (slim state: base pointers + stride pattern) ----
    int srow0 = tid >> 3, sc8 = tid & 7;          // p adds 32 to row, chunk unchanged
    const __half* Asrc0 = A + (size_t)(bm * GBM + srow0) * K + sc8 * 8;
    const __half* Bsrc0 = B + (size_t)(bn * GBN + srow0) * K + sc8 * 8;
    int sdst0 = srow0 * 64 + ((sc8 ^ (srow0 & 7)) << 3);   // p adds 32*64

    float acc[2][8][4];
    #pragma unroll
    for (int mt = 0; mt < 2; mt++)
        #pragma unroll
        for (int nt = 0; nt < 8; nt++)
            #pragma unroll
            for (int q = 0; q < 4; q++) acc[mt][nt][q] = 0.f;

    int kt = K / GBK;

    // ---- ldmatrix per-lane addressing ----
    unsigned smbase = (unsigned)__cvta_generic_to_shared(smh);
    int l7 = lane & 7;
    int arow = wm * 32 + l7 + ((lane >> 3) & 1) * 8;   // +16 per mt
    int brow = wn * 64 + l7 + (lane >> 4) * 8;         // +16 per nt-pair
    unsigned abyte0 = smbase + arow * 128;
    unsigned bbyte0 = smbase + TILE_H * 2 + brow * 128;
    int kA = lane >> 4;          // chunk bit for A
    int kB = (lane >> 3) & 1;    // chunk bit for B

    // ---- prologue: stage ktiles 0,1 ----
    #pragma unroll
    for (int s = 0; s < NSTAGE - 1; s++) {
        #pragma unroll
        for (int p = 0; p < 4; p++) {
            cp16(smh + s * STAGE_H + sdst0 + p * 2048,
                 Asrc0 + (size_t)(32 * p) * K + s * GBK);
            cp16(smh + s * STAGE_H + TILE_H + sdst0 + p * 2048,
                 Bsrc0 + (size_t)(32 * p) * K + s * GBK);
        }
        cp_commit();
    }

    for (int kb = 0; kb < kt; ++kb) {
        int cur = kb % NSTAGE;
        if (kb + 2 < kt) {
            int nst = (kb + 2) % NSTAGE;
            #pragma unroll
            for (int p = 0; p < 4; p++) {
                cp16(smh + nst * STAGE_H + sdst0 + p * 2048,
                     Asrc0 + (size_t)(32 * p) * K + (kb + 2) * GBK);
                cp16(smh + nst * STAGE_H + TILE_H + sdst0 + p * 2048,
                     Bsrc0 + (size_t)(32 * p) * K + (kb + 2) * GBK);
            }
            cp_commit();
            cp_wait<2>();
        } else if (kb == kt - 2) {
            cp_wait<1>();
        } else {
            cp_wait<0>();
        }
        __syncthreads();

        unsigned aB = abyte0 + cur * (STAGE_H * 2);
        unsigned bB = bbyte0 + cur * (STAGE_H * 2);

        #pragma unroll
        for (int kc = 0; kc < 4; kc++) {
            unsigned fa[2][4];
            #pragma unroll
            for (int mt = 0; mt < 2; mt++)
                ldsm4(fa[mt], aB + mt * (16 * 128) + ((unsigned)((2 * kc + kA) ^ l7) << 4));
            unsigned fb[4][4];
            #pragma unroll
            for (int p = 0; p < 4; p++)
                ldsm4(fb[p], bB + p * (16 * 128) + ((unsigned)((2 * kc + kB) ^ l7) << 4));
            #pragma unroll
            for (int mt = 0; mt < 2; mt++)
                #pragma unroll
                for (int nt = 0; nt < 8; nt++)
                    mma_f16(acc[mt][nt],
                            fa[mt][0], fa[mt][1], fa[mt][2], fa[mt][3],
                            fb[nt >> 1][(nt & 1) * 2], fb[nt >> 1][(nt & 1) * 2 + 1]);
        }
        __syncthreads();
    }

    // ---- epilogue ----
    int row0g = bm * GBM + wm * 32;
    int col0g = bn * GBN + wn * 64;
    #pragma unroll
    for (int mt = 0; mt < 2; mt++)
        #pragma unroll
        for (int nt = 0; nt < 8; nt++)
            #pragma unroll
            for (int h2 = 0; h2 < 2; h2++) {
                int row = row0g + mt * 16 + h2 * 8 + g;
                int col = col0g + nt * 8 + 2 * c;
                float vx = acc[mt][nt][2 * h2 + 0] + bias[col];
                float vy = acc[mt][nt][2 * h2 + 1] + bias[col + 1];
                size_t off = (size_t)row * N + col;
                if (EPI == 2) {
                    __half* Ch = (__half*)Cv;
                    *(__half2*)(Ch + off) =
                        __floats2half2_rn(gelu_exact(vx), gelu_exact(vy));
                } else {
                    float* Cf = (float*)Cv;
                    if (EPI == 1) {
                        float2 r = *(const float2*)(res + off);
                        vx += r.x; vy += r.y;
                    }
                    *(float2*)(Cf + off) = make_float2(vx, vy);
                }
            }
}

// ============================ tf32 tensor-core flash attention ============================
#define SQ_STR 132
#define SK_STR 132
#define SV_STR 136
#define SP_STR 68
#define ATT_SMEM ((128*SQ_STR + 64*SK_STR + 64*SV_STR + 128*SP_STR) * 4)
#define NEG_BIG (-1e30f)

__global__ void __launch_bounds__(256, 1) attn_kernel(
    const float* __restrict__ qkv, const float* __restrict__ slopes,
    __half* __restrict__ out)
{
    extern __shared__ float sm[];
    float* Qs = sm;
    float* Ks = Qs + 128 * SQ_STR;
    float* Vs = Ks + 64 * SK_STR;
    float* Ps = Vs + 64 * SV_STR;

    int qi = blockIdx.x, h = blockIdx.y, b = blockIdx.z;
    int tid = threadIdx.x, warp = tid >> 5, lane = tid & 31;
    int g = lane >> 2, c = lane & 3;
    int q0 = qi * 128;
    float slope = slopes[h];
    const float scale = 0.08838834764831845f;

    const float* qbase = qkv + (size_t)(b * SEQ) * QKV_N + h * HD;
    const float* kbase = qbase + D_MODEL;
    const float* vbase = qbase + 2 * D_MODEL;

    for (int i = tid; i < 128 * 32; i += 256) {
        int r = i >> 5, f4 = i & 31;
        float4 v = *(const float4*)(qbase + (size_t)(q0 + r) * QKV_N + f4 * 4);
        float* d = &Qs[r * SQ_STR + f4 * 4];
        d[0] = tf32r(v.x * scale); d[1] = tf32r(v.y * scale);
        d[2] = tf32r(v.z * scale); d[3] = tf32r(v.w * scale);
    }

    float m0 = NEG_BIG, m1 = NEG_BIG, l0 = 0.f, l1 = 0.f;
    float oc[16][4];
    #pragma unroll
    for (int nt = 0; nt < 16; nt++)
        #pragma unroll
        for (int q = 0; q < 4; q++) oc[nt][q] = 0.f;

    int rowA = 16 * warp + g;
    int qr0 = q0 + rowA, qr1 = qr0 + 8;
    const float* qa0 = &Qs[rowA * SQ_STR];
    const float* qa1 = qa0 + 8 * SQ_STR;
    float* pw0 = &Ps[rowA * SP_STR];
    float* pw1 = pw0 + 8 * SP_STR;

    int ntiles = 2 * qi + 2;
    for (int jt = 0; jt < ntiles; jt++) {
        int j0 = jt * 64;
        __syncthreads();
        for (int i = tid; i < 64 * 32; i += 256) {
            int r = i >> 5, f4 = i & 31;
            float4 kv = *(const float4*)(kbase + (size_t)(j0 + r) * QKV_N + f4 * 4);
            float* kd = &Ks[r * SK_STR + f4 * 4];
            kd[0] = tf32r(kv.x); kd[1] = tf32r(kv.y);
            kd[2] = tf32r(kv.z); kd[3] = tf32r(kv.w);
            float4 vv = *(const float4*)(vbase + (size_t)(j0 + r) * QKV_N + f4 * 4);
            float* vd = &Vs[r * SV_STR + f4 * 4];
            vd[0] = tf32r(vv.x); vd[1] = tf32r(vv.y);
            vd[2] = tf32r(vv.z); vd[3] = tf32r(vv.w);
        }
        __syncthreads();

        float sc[8][4];
        #pragma unroll
        for (int nt = 0; nt < 8; nt++)
            #pragma unroll
            for (int q = 0; q < 4; q++) sc[nt][q] = 0.f;

        #pragma unroll 4
        for (int s = 0; s < 16; s++) {
            int k0 = 8 * s;
            float a0 = qa0[k0 + c];
            float a1 = qa1[k0 + c];
            float a2 = qa0[k0 + c + 4];
            float a3 = qa1[k0 + c + 4];
            #pragma unroll
            for (int nt = 0; nt < 8; nt++) {
                const float* kr = &Ks[(nt * 8 + g) * SK_STR + k0];
                mma_tf32(sc[nt], a0, a1, a2, a3, kr[c], kr[c + 4]);
            }
        }

        bool masked = (jt >= 2 * qi);
        float tm0 = NEG_BIG, tm1 = NEG_BIG;
        #pragma unroll
        for (int nt = 0; nt < 8; nt++) {
            #pragma unroll
            for (int j = 0; j < 2; j++) {
                int col = j0 + nt * 8 + 2 * c + j;
                float d0 = (float)(col - qr0);
                float d1 = (float)(col - qr1);
                float s0 = sc[nt][j]     + slope * d0;
                float s1 = sc[nt][2 + j] + slope * d1;
                if (masked) {
                    if (col > qr0) s0 = NEG_BIG;
                    if (col > qr1) s1 = NEG_BIG;
                }
                sc[nt][j] = s0; sc[nt][2 + j] = s1;
                tm0 = fmaxf(tm0, s0); tm1 = fmaxf(tm1, s1);
            }
        }
        #pragma unroll
        for (int o = 1; o < 4; o <<= 1) {
            tm0 = fmaxf(tm0, __shfl_xor_sync(0xffffffffu, tm0, o));
            tm1 = fmaxf(tm1, __shfl_xor_sync(0xffffffffu, tm1, o));
        }
        float mn0 = fmaxf(m0, tm0), mn1 = fmaxf(m1, tm1);
        float alpha0 = __expf(m0 - mn0), alpha1 = __expf(m1 - mn1);
        float rs0 = 0.f, rs1 = 0.f;
        #pragma unroll
        for (int nt = 0; nt < 8; nt++) {
            #pragma unroll
            for (int j = 0; j < 2; j++) {
                float p0 = __expf(sc[nt][j]     - mn0);
                float p1 = __expf(sc[nt][2 + j] - mn1);
                sc[nt][j] = p0; sc[nt][2 + j] = p1;
                rs0 += p0; rs1 += p1;
            }
        }
        #pragma unroll
        for (int o = 1; o < 4; o <<= 1) {
            rs0 += __shfl_xor_sync(0xffffffffu, rs0, o);
            rs1 += __shfl_xor_sync(0xffffffffu, rs1, o);
        }
        l0 = l0 * alpha0 + rs0;
        l1 = l1 * alpha1 + rs1;
        m0 = mn0; m1 = mn1;
        #pragma unroll
        for (int nt = 0; nt < 16; nt++) {
            oc[nt][0] *= alpha0; oc[nt][1] *= alpha0;
            oc[nt][2] *= alpha1; oc[nt][3] *= alpha1;
        }

        #pragma unroll
        for (int nt = 0; nt < 8; nt++) {
            float2 w0 = make_float2(tf32r(sc[nt][0]), tf32r(sc[nt][1]));
            float2 w1 = make_float2(tf32r(sc[nt][2]), tf32r(sc[nt][3]));
            *(float2*)&pw0[nt * 8 + 2 * c] = w0;
            *(float2*)&pw1[nt * 8 + 2 * c] = w1;
        }
        __syncwarp();

        #pragma unroll 2
        for (int s = 0; s < 8; s++) {
            int k0 = 8 * s;
            float a0 = pw0[k0 + c];
            float a1 = pw1[k0 + c];
            float a2 = pw0[k0 + c + 4];
            float a3 = pw1[k0 + c + 4];
            const float* v0r = &Vs[(k0 + c) * SV_STR + g];
            const float* v1r = &Vs[(k0 + c + 4) * SV_STR + g];
            #pragma unroll
            for (int nt = 0; nt < 16; nt++)
                mma_tf32(oc[nt], a0, a1, a2, a3, v0r[nt * 8], v1r[nt * 8]);
        }
    }

    float inv0 = 1.f / l0, inv1 = 1.f / l1;
    __half* ob  = out + (size_t)(b * SEQ + qr0) * D_MODEL + h * HD;
    __half* ob1 = ob + 8 * D_MODEL;
    #pragma unroll
    for (int nt = 0; nt < 16; nt++) {
        *(__half2*)&ob[nt * 8 + 2 * c] =
            __floats2half2_rn(oc[nt][0] * inv0, oc[nt][1] * inv0);
        *(__half2*)&ob1[nt * 8 + 2 * c] =
            __floats2half2_rn(oc[nt][2] * inv1, oc[nt][3] * inv1);
    }
}

// ============================ launch ============================
extern "C" void kernel_launch(void* const* d_in, const int* in_sizes, int n_in,
                              void* d_out, int out_size)
{
    const float* x      = (const float*)d_in[0];
    const float* ln1_w  = (const float*)d_in[1];
    const float* ln1_b  = (const float*)d_in[2];
    const float* Wqkv   = (const float*)d_in[3];
    const float* bqkv   = (const float*)d_in[4];
    const float* Wo     = (const float*)d_in[5];
    const float* bo     = (const float*)d_in[6];
    const float* ln2_w  = (const float*)d_in[7];
    const float* ln2_b  = (const float*)d_in[8];
    const float* W1     = (const float*)d_in[9];
    const float* b1     = (const float*)d_in[10];
    const float* W2     = (const float*)d_in[11];
    const float* b2     = (const float*)d_in[12];
    const float* slopes = (const float*)d_in[13];
    float* out = (float*)d_out;

    __half *h, *attn, *mlp, *wh;
    float *qkv;
    cudaGetSymbolAddress((void**)&h,    g_h);
    cudaGetSymbolAddress((void**)&qkv,  g_qkv);
    cudaGetSymbolAddress((void**)&attn, g_attn);
    cudaGetSymbolAddress((void**)&mlp,  g_mlp);
    cudaGetSymbolAddress((void**)&wh,   g_wh);

    cudaFuncSetAttribute(attn_kernel,
                         cudaFuncAttributeMaxDynamicSharedMemorySize, ATT_SMEM);
    cudaFuncSetAttribute(gemm_kernel<0>,
                         cudaFuncAttributeMaxDynamicSharedMemorySize, GEMM_SMEM);
    cudaFuncSetAttribute(gemm_kernel<1>,
                         cudaFuncAttributeMaxDynamicSharedMemorySize, GEMM_SMEM);
    cudaFuncSetAttribute(gemm_kernel<2>,
                         cudaFuncAttributeMaxDynamicSharedMemorySize, GEMM_SMEM);

    // 0. convert weights to half
    {
        int n8;
        n8 = 3 * D_MODEL * D_MODEL / 8;
        to_half_kernel<<<(n8 + 255) / 256, 256>>>((const float4*)Wqkv,
            (uint4*)(wh + WQKV_OFF), n8);
        n8 = D_MODEL * D_MODEL / 8;
        to_half_kernel<<<(n8 + 255) / 256, 256>>>((const float4*)Wo,
            (uint4*)(wh + WO_OFF), n8);
        n8 = D_FF * D_MODEL / 8;
        to_half_kernel<<<(n8 + 255) / 256, 256>>>((const float4*)W1,
            (uint4*)(wh + W1_OFF), n8);
        n8 = D_MODEL * D_FF / 8;
        to_half_kernel<<<(n8 + 255) / 256, 256>>>((const float4*)W2,
            (uint4*)(wh + W2_OFF), n8);
    }

    // 1. LN1 -> half
    ln_kernel<<<ROWS, 256>>>(x, ln1_w, ln1_b, h);
    // 2. QKV GEMM (half x half -> fp32)
    gemm_kernel<0><<<dim3(QKV_N / GBN, ROWS / GBM), 256, GEMM_SMEM>>>(
        h, wh + WQKV_OFF, bqkv, nullptr, qkv, ROWS, QKV_N, D_MODEL);
    // 3. Flash attention with ALiBi (tf32 TC) -> half
    attn_kernel<<<dim3(SEQ / 128, NH, BATCH), 256, ATT_SMEM>>>(qkv, slopes, attn);
    // 4. O projection + residual (x) -> d_out fp32
    gemm_kernel<1><<<dim3(D_MODEL / GBN, ROWS / GBM), 256, GEMM_SMEM>>>(
        attn, wh + WO_OFF, bo, x, out, ROWS, D_MODEL, D_MODEL);
    // 5. LN2 -> half
    ln_kernel<<<ROWS, 256>>>(out, ln2_w, ln2_b, h);
    // 6. MLP up + GELU -> half
    gemm_kernel<2><<<dim3(D_FF / GBN, ROWS / GBM), 256, GEMM_SMEM>>>(
        h, wh + W1_OFF, b1, nullptr, mlp, ROWS, D_FF, D_MODEL);
    // 7. MLP down + residual (x1 in d_out) -> d_out fp32 final
    gemm_kernel<1><<<dim3(D_MODEL / GBN, ROWS / GBM), 256, GEMM_SMEM>>>(
        mlp, wh + W2_OFF, b2, out, out, ROWS, D_MODEL, D_FF);
}

// round 10
// speedup vs baseline: 4.8794x; 1.1573x over previous
#include <cuda_runtime.h>
#include <cuda_fp16.h>
#include <math.h>

#define D_MODEL 2048
#define NH 16
#define HD 128
#define SEQ 2048
#define BATCH 4
#define ROWS (BATCH * SEQ)       // 8192
#define D_FF 8192
#define QKV_N (3 * D_MODEL)      // 6144

// -------- scratch (static device globals; no cudaMalloc allowed) --------
__device__ __half g_h[(size_t)ROWS * D_MODEL];     // LN output (half)
__device__ __half g_qkv[(size_t)ROWS * QKV_N];     // fused QKV (half)
__device__ __half g_attn[(size_t)ROWS * D_MODEL];  // attention out (half)
__device__ __half g_mlp[(size_t)ROWS * D_FF];      // MLP hidden (half)
// half weights: Wqkv | Wo | W1 | W2
#define WQKV_OFF 0
#define WO_OFF   (3 * D_MODEL * D_MODEL)
#define W1_OFF   (WO_OFF + D_MODEL * D_MODEL)
#define W2_OFF   (W1_OFF + D_FF * D_MODEL)
#define WR_TOTAL (W2_OFF + D_MODEL * D_FF)
__device__ __half g_wh[(size_t)WR_TOTAL];

// ============================ helpers ============================
__device__ __forceinline__ void mma_f16(float* c,
    unsigned a0, unsigned a1, unsigned a2, unsigned a3,
    unsigned b0, unsigned b1)
{
    asm volatile(
        "mma.sync.aligned.m16n8k16.row.col.f32.f16.f16.f32 "
        "{%0,%1,%2,%3}, {%4,%5,%6,%7}, {%8,%9}, {%0,%1,%2,%3};"
        : "+f"(c[0]), "+f"(c[1]), "+f"(c[2]), "+f"(c[3])
        : "r"(a0), "r"(a1), "r"(a2), "r"(a3), "r"(b0), "r"(b1));
}

__device__ __forceinline__ void ldsm4(unsigned* r, unsigned addr) {
    asm volatile(
        "ldmatrix.sync.aligned.m8n8.x4.shared.b16 {%0,%1,%2,%3}, [%4];"
        : "=r"(r[0]), "=r"(r[1]), "=r"(r[2]), "=r"(r[3]) : "r"(addr));
}
__device__ __forceinline__ void ldsm4t(unsigned* r, unsigned addr) {
    asm volatile(
        "ldmatrix.sync.aligned.m8n8.x4.trans.shared.b16 {%0,%1,%2,%3}, [%4];"
        : "=r"(r[0]), "=r"(r[1]), "=r"(r[2]), "=r"(r[3]) : "r"(addr));
}

__device__ __forceinline__ void cp16(void* dst_sh, const void* src) {
    unsigned sa = (unsigned)__cvta_generic_to_shared(dst_sh);
    asm volatile("cp.async.cg.shared.global [%0], [%1], 16;" :: "r"(sa), "l"(src));
}
__device__ __forceinline__ void cp_commit() {
    asm volatile("cp.async.commit_group;");
}
template <int N>
__device__ __forceinline__ void cp_wait() {
    asm volatile("cp.async.wait_group %0;" :: "n"(N));
}

__device__ __forceinline__ float gelu_exact(float v) {
    return 0.5f * v * (1.0f + erff(v * 0.70710678118654752f));
}

__device__ __forceinline__ unsigned h2u(__half2 h) {
    unsigned u;
    *(__half2*)&u = h;
    return u;
}

// ============================ fp32 -> fp16 convert ============================
__global__ void __launch_bounds__(256) to_half_kernel(
    const float4* __restrict__ src, uint4* __restrict__ dst, int n8)
{
    int i = blockIdx.x * 256 + threadIdx.x;
    if (i < n8) {
        float4 v0 = src[2 * i], v1 = src[2 * i + 1];
        uint4 o;
        o.x = h2u(__floats2half2_rn(v0.x, v0.y));
        o.y = h2u(__floats2half2_rn(v0.z, v0.w));
        o.z = h2u(__floats2half2_rn(v1.x, v1.y));
        o.w = h2u(__floats2half2_rn(v1.z, v1.w));
        dst[i] = o;
    }
}

// ============================ LayerNorm (half output) ============================
__global__ void __launch_bounds__(256) ln_kernel(
    const float* __restrict__ x, const float* __restrict__ g,
    const float* __restrict__ b, __half* __restrict__ out)
{
    __shared__ float red[2][8];
    int row = blockIdx.x, tid = threadIdx.x;
    const float4* xr = (const float4*)(x + (size_t)row * D_MODEL);
    float4 v0 = xr[tid];
    float4 v1 = xr[tid + 256];
    float s  = v0.x + v0.y + v0.z + v0.w + v1.x + v1.y + v1.z + v1.w;
    float s2 = v0.x*v0.x + v0.y*v0.y + v0.z*v0.z + v0.w*v0.w
             + v1.x*v1.x + v1.y*v1.y + v1.z*v1.z + v1.w*v1.w;
    #pragma unroll
    for (int o = 16; o; o >>= 1) {
        s  += __shfl_xor_sync(0xffffffffu, s,  o);
        s2 += __shfl_xor_sync(0xffffffffu, s2, o);
    }
    if ((tid & 31) == 0) { red[0][tid >> 5] = s; red[1][tid >> 5] = s2; }
    __syncthreads();
    if (tid < 32) {
        float a = (tid < 8) ? red[0][tid] : 0.f;
        float c = (tid < 8) ? red[1][tid] : 0.f;
        #pragma unroll
        for (int o = 4; o; o >>= 1) {
            a += __shfl_xor_sync(0xffffffffu, a, o);
            c += __shfl_xor_sync(0xffffffffu, c, o);
        }
        if (tid == 0) { red[0][0] = a; red[1][0] = c; }
    }
    __syncthreads();
    float mean = red[0][0] * (1.f / D_MODEL);
    float var  = red[1][0] * (1.f / D_MODEL) - mean * mean;
    float rstd = rsqrtf(var + 1e-5f);

    const float4* gr = (const float4*)g;
    const float4* br = (const float4*)b;
    __half2* orow = (__half2*)(out + (size_t)row * D_MODEL);
    #pragma unroll
    for (int p = 0; p < 2; p++) {
        float4 v = p ? v1 : v0;
        float4 gw = gr[tid + p * 256];
        float4 bw = br[tid + p * 256];
        orow[2 * (tid + p * 256) + 0] = __floats2half2_rn(
            (v.x - mean) * rstd * gw.x + bw.x,
            (v.y - mean) * rstd * gw.y + bw.y);
        orow[2 * (tid + p * 256) + 1] = __floats2half2_rn(
            (v.z - mean) * rstd * gw.z + bw.z,
            (v.w - mean) * rstd * gw.w + bw.w);
    }
}

// ============================ fp16 mma GEMM: cp.async 3-stage + ldmatrix ============================
// EPI: 0 = bias -> half; 1 = bias + fp32 residual -> fp32; 2 = bias + GELU -> half
#define GBM 128
#define GBN 128
#define GBK 64
#define TILE_H (128 * 64)
#define NSTAGE 3
#define STAGE_H (2 * TILE_H)
#define GEMM_SMEM (NSTAGE * STAGE_H * 2)  // 98304 B

template <int EPI>
__global__ void __launch_bounds__(256, 2) gemm_kernel(
    const __half* __restrict__ A, const __half* __restrict__ B,
    const float* __restrict__ bias, const float* __restrict__ res,
    void* __restrict__ Cv, int M, int N, int K)
{
    extern __shared__ __half smh[];
    int tid = threadIdx.x;
    int bm = blockIdx.y, bn = blockIdx.x;
    int warp = tid >> 5, lane = tid & 31;
    int wm = warp >> 1, wn = warp & 1;
    int g = lane >> 2, c = lane & 3;

    int srow0 = tid >> 3, sc8 = tid & 7;
    const __half* Asrc0 = A + (size_t)(bm * GBM + srow0) * K + sc8 * 8;
    const __half* Bsrc0 = B + (size_t)(bn * GBN + srow0) * K + sc8 * 8;
    int sdst0 = srow0 * 64 + ((sc8 ^ (srow0 & 7)) << 3);

    float acc[2][8][4];
    #pragma unroll
    for (int mt = 0; mt < 2; mt++)
        #pragma unroll
        for (int nt = 0; nt < 8; nt++)
            #pragma unroll
            for (int q = 0; q < 4; q++) acc[mt][nt][q] = 0.f;

    int kt = K / GBK;

    unsigned smbase = (unsigned)__cvta_generic_to_shared(smh);
    int l7 = lane & 7;
    int arow = wm * 32 + l7 + ((lane >> 3) & 1) * 8;
    int brow = wn * 64 + l7 + (lane >> 4) * 8;
    unsigned abyte0 = smbase + arow * 128;
    unsigned bbyte0 = smbase + TILE_H * 2 + brow * 128;
    int kA = lane >> 4;
    int kB = (lane >> 3) & 1;

    #pragma unroll
    for (int s = 0; s < NSTAGE - 1; s++) {
        #pragma unroll
        for (int p = 0; p < 4; p++) {
            cp16(smh + s * STAGE_H + sdst0 + p * 2048,
                 Asrc0 + (size_t)(32 * p) * K + s * GBK);
            cp16(smh + s * STAGE_H + TILE_H + sdst0 + p * 2048,
                 Bsrc0 + (size_t)(32 * p) * K + s * GBK);
        }
        cp_commit();
    }

    for (int kb = 0; kb < kt; ++kb) {
        int cur = kb % NSTAGE;
        if (kb + 2 < kt) {
            int nst = (kb + 2) % NSTAGE;
            #pragma unroll
            for (int p = 0; p < 4; p++) {
                cp16(smh + nst * STAGE_H + sdst0 + p * 2048,
                     Asrc0 + (size_t)(32 * p) * K + (kb + 2) * GBK);
                cp16(smh + nst * STAGE_H + TILE_H + sdst0 + p * 2048,
                     Bsrc0 + (size_t)(32 * p) * K + (kb + 2) * GBK);
            }
            cp_commit();
            cp_wait<2>();
        } else if (kb == kt - 2) {
            cp_wait<1>();
        } else {
            cp_wait<0>();
        }
        __syncthreads();

        unsigned aB = abyte0 + cur * (STAGE_H * 2);
        unsigned bB = bbyte0 + cur * (STAGE_H * 2);

        #pragma unroll
        for (int kc = 0; kc < 4; kc++) {
            unsigned fa[2][4];
            #pragma unroll
            for (int mt = 0; mt < 2; mt++)
                ldsm4(fa[mt], aB + mt * (16 * 128) + ((unsigned)((2 * kc + kA) ^ l7) << 4));
            unsigned fb[4][4];
            #pragma unroll
            for (int p = 0; p < 4; p++)
                ldsm4(fb[p], bB + p * (16 * 128) + ((unsigned)((2 * kc + kB) ^ l7) << 4));
            #pragma unroll
            for (int mt = 0; mt < 2; mt++)
                #pragma unroll
                for (int nt = 0; nt < 8; nt++)
                    mma_f16(acc[mt][nt],
                            fa[mt][0], fa[mt][1], fa[mt][2], fa[mt][3],
                            fb[nt >> 1][(nt & 1) * 2], fb[nt >> 1][(nt & 1) * 2 + 1]);
        }
        __syncthreads();
    }

    int row0g = bm * GBM + wm * 32;
    int col0g = bn * GBN + wn * 64;
    #pragma unroll
    for (int mt = 0; mt < 2; mt++)
        #pragma unroll
        for (int nt = 0; nt < 8; nt++)
            #pragma unroll
            for (int h2 = 0; h2 < 2; h2++) {
                int row = row0g + mt * 16 + h2 * 8 + g;
                int col = col0g + nt * 8 + 2 * c;
                float vx = acc[mt][nt][2 * h2 + 0] + bias[col];
                float vy = acc[mt][nt][2 * h2 + 1] + bias[col + 1];
                size_t off = (size_t)row * N + col;
                if (EPI == 0) {
                    __half* Ch = (__half*)Cv;
                    *(__half2*)(Ch + off) = __floats2half2_rn(vx, vy);
                } else if (EPI == 2) {
                    __half* Ch = (__half*)Cv;
                    *(__half2*)(Ch + off) =
                        __floats2half2_rn(gelu_exact(vx), gelu_exact(vy));
                } else {
                    float* Cf = (float*)Cv;
                    float2 r = *(const float2*)(res + off);
                    vx += r.x; vy += r.y;
                    *(float2*)(Cf + off) = make_float2(vx, vy);
                }
            }
}

// ============================ fp16 tensor-core flash attention ============================
// CTA: 128 q x 64-key tiles, 8 warps (16 q-rows each). All tiles in swizzled
// half format: 64-half rows (128 B), 16B chunk c8 ^ (row&7). QK^T and P.V via
// m16n8k16 with ldmatrix (V via ldmatrix.trans). Softmax fp32, P in half.
#define QS_OFF 0                     // 2 tiles x 128x64 halfs
#define KS_OFF (2 * 128 * 64)        // 2 tiles x 64x64
#define VS_OFF (KS_OFF + 2 * 64 * 64)
#define PS_OFF (VS_OFF + 2 * 64 * 64)  // 8 warps x 16x64
#define ATT_HALFS (PS_OFF + 8 * 16 * 64)
#define ATT_SMEM (ATT_HALFS * 2)     // 81920 B
#define NEG_BIG (-1e30f)

__global__ void __launch_bounds__(256, 1) attn_kernel(
    const __half* __restrict__ qkv, const float* __restrict__ slopes,
    __half* __restrict__ out)
{
    extern __shared__ __half smA[];
    int qi = blockIdx.x, h = blockIdx.y, b = blockIdx.z;
    int tid = threadIdx.x, warp = tid >> 5, lane = tid & 31;
    int g = lane >> 2, c = lane & 3, l7 = lane & 7;
    int q0 = qi * 128;
    float slope = slopes[h];
    const float scale = 0.08838834764831845f;   // 1/sqrt(128)

    const __half* qb = qkv + (size_t)(b * SEQ) * QKV_N + h * HD;
    const __half* kb = qb + D_MODEL;
    const __half* vb = qb + 2 * D_MODEL;

    unsigned smbase = (unsigned)__cvta_generic_to_shared(smA);
    __half* Pw = smA + PS_OFF + warp * 1024;
    unsigned pbase = smbase + (PS_OFF + warp * 1024) * 2;

    // stage Q (resident): 128 rows x 16 chunks of 16B
    for (int i = tid; i < 2048; i += 256) {
        int row = i >> 4, cc = i & 15;
        int t = cc >> 3, cw = cc & 7;
        cp16(smA + QS_OFF + t * 8192 + row * 64 + ((cw ^ (row & 7)) << 3),
             qb + (size_t)(q0 + row) * QKV_N + cc * 8);
    }
    cp_commit();

    float m0 = NEG_BIG, m1 = NEG_BIG, l0 = 0.f, l1 = 0.f;
    float oc[16][4];
    #pragma unroll
    for (int nt = 0; nt < 16; nt++)
        #pragma unroll
        for (int q = 0; q < 4; q++) oc[nt][q] = 0.f;

    int rowA = 16 * warp + g;
    int qr0 = q0 + rowA, qr1 = qr0 + 8;

    // ldmatrix lane geometry
    int a_roff = ((lane >> 3) & 1) * 8 + l7;   // A matrices: row = base + a_roff
    int a_csel = lane >> 4;                    // A chunk add
    int b_roff = (lane >> 4) * 8 + l7;         // B (K) row offset
    int b_csel = (lane >> 3) & 1;              // B chunk add
    int v_roff = ((lane >> 3) & 1) * 8 + l7;   // V trans: key offset
    int v_csel = lane >> 4;                    // V chunk add (n dir)

    int ntiles = 2 * qi + 2;
    for (int jt = 0; jt < ntiles; jt++) {
        int j0 = jt * 64;
        __syncthreads();   // previous tile's K/V reads done
        // stage K, V: each 64 rows x 16 chunks
        for (int i = tid; i < 1024; i += 256) {
            int row = i >> 4, cc = i & 15;
            int t = cc >> 3, cw = cc & 7;
            int d = row * 64 + ((cw ^ (row & 7)) << 3);
            cp16(smA + KS_OFF + t * 4096 + d, kb + (size_t)(j0 + row) * QKV_N + cc * 8);
            cp16(smA + VS_OFF + t * 4096 + d, vb + (size_t)(j0 + row) * QKV_N + cc * 8);
        }
        cp_commit();
        cp_wait<0>();
        __syncthreads();

        // ---- S = Q K^T ----
        float sc[8][4];
        #pragma unroll
        for (int nt = 0; nt < 8; nt++)
            #pragma unroll
            for (int q = 0; q < 4; q++) sc[nt][q] = 0.f;

        #pragma unroll
        for (int kc = 0; kc < 8; kc++) {
            int t = kc >> 2, k2 = kc & 3;
            unsigned fa[4];
            {
                int row = warp * 16 + a_roff;
                unsigned addr = smbase +
                    (QS_OFF + t * 8192 + row * 64 + (((k2 * 2 + a_csel) ^ l7) << 3)) * 2;
                ldsm4(fa, addr);
            }
            unsigned fb[4][4];
            #pragma unroll
            for (int p = 0; p < 4; p++) {
                int key = 16 * p + b_roff;
                unsigned addr = smbase +
                    (KS_OFF + t * 4096 + key * 64 + (((k2 * 2 + b_csel) ^ l7) << 3)) * 2;
                ldsm4(fb[p], addr);
            }
            #pragma unroll
            for (int nt = 0; nt < 8; nt++)
                mma_f16(sc[nt], fa[0], fa[1], fa[2], fa[3],
                        fb[nt >> 1][(nt & 1) * 2], fb[nt >> 1][(nt & 1) * 2 + 1]);
        }

        // ---- scale + ALiBi + causal + online softmax (fp32) ----
        bool masked = (jt >= 2 * qi);
        float tm0 = NEG_BIG, tm1 = NEG_BIG;
        #pragma unroll
        for (int nt = 0; nt < 8; nt++) {
            #pragma unroll
            for (int j = 0; j < 2; j++) {
                int col = j0 + nt * 8 + 2 * c + j;
                float s0 = sc[nt][j]     * scale + slope * (float)(col - qr0);
                float s1 = sc[nt][2 + j] * scale + slope * (float)(col - qr1);
                if (masked) {
                    if (col > qr0) s0 = NEG_BIG;
                    if (col > qr1) s1 = NEG_BIG;
                }
                sc[nt][j] = s0; sc[nt][2 + j] = s1;
                tm0 = fmaxf(tm0, s0); tm1 = fmaxf(tm1, s1);
            }
        }
        #pragma unroll
        for (int o = 1; o < 4; o <<= 1) {
            tm0 = fmaxf(tm0, __shfl_xor_sync(0xffffffffu, tm0, o));
            tm1 = fmaxf(tm1, __shfl_xor_sync(0xffffffffu, tm1, o));
        }
        float mn0 = fmaxf(m0, tm0), mn1 = fmaxf(m1, tm1);
        float alpha0 = __expf(m0 - mn0), alpha1 = __expf(m1 - mn1);
        float rs0 = 0.f, rs1 = 0.f;
        #pragma unroll
        for (int nt = 0; nt < 8; nt++) {
            #pragma unroll
            for (int j = 0; j < 2; j++) {
                float p0 = __expf(sc[nt][j]     - mn0);
                float p1 = __expf(sc[nt][2 + j] - mn1);
                sc[nt][j] = p0; sc[nt][2 + j] = p1;
                rs0 += p0; rs1 += p1;
            }
        }
        #pragma unroll
        for (int o = 1; o < 4; o <<= 1) {
            rs0 += __shfl_xor_sync(0xffffffffu, rs0, o);
            rs1 += __shfl_xor_sync(0xffffffffu, rs1, o);
        }
        l0 = l0 * alpha0 + rs0;
        l1 = l1 * alpha1 + rs1;
        m0 = mn0; m1 = mn1;
        #pragma unroll
        for (int nt = 0; nt < 16; nt++) {
            oc[nt][0] *= alpha0; oc[nt][1] *= alpha0;
            oc[nt][2] *= alpha1; oc[nt][3] *= alpha1;
        }

        // ---- stage P (half, swizzled 16x64 per warp) ----
        __syncwarp();
        #pragma unroll
        for (int nt = 0; nt < 8; nt++) {
            *(__half2*)(Pw + g * 64 + ((nt ^ (g & 7)) << 3) + 2 * c) =
                __floats2half2_rn(sc[nt][0], sc[nt][1]);
            *(__half2*)(Pw + (g + 8) * 64 + ((nt ^ (g & 7)) << 3) + 2 * c) =
                __floats2half2_rn(sc[nt][2], sc[nt][3]);
        }
        __syncwarp();

        // ---- O += P @ V ----
        #pragma unroll
        for (int kc2 = 0; kc2 < 4; kc2++) {
            unsigned fa[4];
            {
                unsigned addr = pbase +
                    (a_roff * 64 + (((kc2 * 2 + a_csel) ^ l7) << 3)) * 2;
                ldsm4(fa, addr);
            }
            unsigned fv[8][4];
            #pragma unroll
            for (int nv = 0; nv < 8; nv++) {
                int t = nv >> 2;
                int cw = (nv & 3) * 2 + v_csel;
                int key = kc2 * 16 + v_roff;
                unsigned addr = smbase +
                    (VS_OFF + t * 4096 + key * 64 + ((cw ^ l7) << 3)) * 2;
                ldsm4t(fv[nv], addr);
            }
            #pragma unroll
            for (int nt = 0; nt < 16; nt++)
                mma_f16(oc[nt], fa[0], fa[1], fa[2], fa[3],
                        fv[nt >> 1][(nt & 1) * 2], fv[nt >> 1][(nt & 1) * 2 + 1]);
        }
    }

    // ---- normalize + write half ----
    float inv0 = 1.f / l0, inv1 = 1.f / l1;
    __half* ob  = out + (size_t)(b * SEQ + qr0) * D_MODEL + h * HD;
    __half* ob1 = ob + 8 * D_MODEL;
    #pragma unroll
    for (int nt = 0; nt < 16; nt++) {
        *(__half2*)&ob[nt * 8 + 2 * c] =
            __floats2half2_rn(oc[nt][0] * inv0, oc[nt][1] * inv0);
        *(__half2*)&ob1[nt * 8 + 2 * c] =
            __floats2half2_rn(oc[nt][2] * inv1, oc[nt][3] * inv1);
    }
}

// ============================ launch ============================
extern "C" void kernel_launch(void* const* d_in, const int* in_sizes, int n_in,
                              void* d_out, int out_size)
{
    const float* x      = (const float*)d_in[0];
    const float* ln1_w  = (const float*)d_in[1];
    const float* ln1_b  = (const float*)d_in[2];
    const float* Wqkv   = (const float*)d_in[3];
    const float* bqkv   = (const float*)d_in[4];
    const float* Wo     = (const float*)d_in[5];
    const float* bo     = (const float*)d_in[6];
    const float* ln2_w  = (const float*)d_in[7];
    const float* ln2_b  = (const float*)d_in[8];
    const float* W1     = (const float*)d_in[9];
    const float* b1     = (const float*)d_in[10];
    const float* W2     = (const float*)d_in[11];
    const float* b2     = (const float*)d_in[12];
    const float* slopes = (const float*)d_in[13];
    float* out = (float*)d_out;

    __half *h, *qkv, *attn, *mlp, *wh;
    cudaGetSymbolAddress((void**)&h,    g_h);
    cudaGetSymbolAddress((void**)&qkv,  g_qkv);
    cudaGetSymbolAddress((void**)&attn, g_attn);
    cudaGetSymbolAddress((void**)&mlp,  g_mlp);
    cudaGetSymbolAddress((void**)&wh,   g_wh);

    cudaFuncSetAttribute(attn_kernel,
                         cudaFuncAttributeMaxDynamicSharedMemorySize, ATT_SMEM);
    cudaFuncSetAttribute(gemm_kernel<0>,
                         cudaFuncAttributeMaxDynamicSharedMemorySize, GEMM_SMEM);
    cudaFuncSetAttribute(gemm_kernel<1>,
                         cudaFuncAttributeMaxDynamicSharedMemorySize, GEMM_SMEM);
    cudaFuncSetAttribute(gemm_kernel<2>,
                         cudaFuncAttributeMaxDynamicSharedMemorySize, GEMM_SMEM);

    // 0. convert weights to half
    {
        int n8;
        n8 = 3 * D_MODEL * D_MODEL / 8;
        to_half_kernel<<<(n8 + 255) / 256, 256>>>((const float4*)Wqkv,
            (uint4*)(wh + WQKV_OFF), n8);
        n8 = D_MODEL * D_MODEL / 8;
        to_half_kernel<<<(n8 + 255) / 256, 256>>>((const float4*)Wo,
            (uint4*)(wh + WO_OFF), n8);
        n8 = D_FF * D_MODEL / 8;
        to_half_kernel<<<(n8 + 255) / 256, 256>>>((const float4*)W1,
            (uint4*)(wh + W1_OFF), n8);
        n8 = D_MODEL * D_FF / 8;
        to_half_kernel<<<(n8 + 255) / 256, 256>>>((const float4*)W2,
            (uint4*)(wh + W2_OFF), n8);
    }

    // 1. LN1 -> half
    ln_kernel<<<ROWS, 256>>>(x, ln1_w, ln1_b, h);
    // 2. QKV GEMM -> half
    gemm_kernel<0><<<dim3(QKV_N / GBN, ROWS / GBM), 256, GEMM_SMEM>>>(
        h, wh + WQKV_OFF, bqkv, nullptr, qkv, ROWS, QKV_N, D_MODEL);
    // 3. Flash attention with ALiBi (fp16 mma) -> half
    attn_kernel<<<dim3(SEQ / 128, NH, BATCH), 256, ATT_SMEM>>>(qkv, slopes, attn);
    // 4. O projection + residual (x) -> d_out fp32
    gemm_kernel<1><<<dim3(D_MODEL / GBN, ROWS / GBM), 256, GEMM_SMEM>>>(
        attn, wh + WO_OFF, bo, x, out, ROWS, D_MODEL, D_MODEL);
    // 5. LN2 -> half
    ln_kernel<<<ROWS, 256>>>(out, ln2_w, ln2_b, h);
    // 6. MLP up + GELU -> half
    gemm_kernel<2><<<dim3(D_FF / GBN, ROWS / GBM), 256, GEMM_SMEM>>>(
        h, wh + W1_OFF, b1, nullptr, mlp, ROWS, D_FF, D_MODEL);
    // 7. MLP down + residual (x1 in d_out) -> d_out fp32 final
    gemm_kernel<1><<<dim3(D_MODEL / GBN, ROWS / GBM), 256, GEMM_SMEM>>>(
        mlp, wh + W2_OFF, b2, out, out, ROWS, D_MODEL, D_FF);
}

// round 11
// speedup vs baseline: 5.0247x; 1.0298x over previous
#include <cuda_runtime.h>
#include <cuda_fp16.h>
#include <math.h>

#define D_MODEL 2048
#define NH 16
#define HD 128
#define SEQ 2048
#define BATCH 4
#define ROWS (BATCH * SEQ)       // 8192
#define D_FF 8192
#define QKV_N (3 * D_MODEL)      // 6144

// -------- scratch (static device globals; no cudaMalloc allowed) --------
__device__ __half g_h[(size_t)ROWS * D_MODEL];     // LN output (half)
__device__ __half g_qkv[(size_t)ROWS * QKV_N];     // fused QKV (half)
__device__ __half g_attn[(size_t)ROWS * D_MODEL];  // attention out (half)
__device__ __half g_mlp[(size_t)ROWS * D_FF];      // MLP hidden (half)
// half weights: Wqkv | Wo | W1 | W2
#define WQKV_OFF 0
#define WO_OFF   (3 * D_MODEL * D_MODEL)
#define W1_OFF   (WO_OFF + D_MODEL * D_MODEL)
#define W2_OFF   (W1_OFF + D_FF * D_MODEL)
#define WR_TOTAL (W2_OFF + D_MODEL * D_FF)
__device__ __half g_wh[(size_t)WR_TOTAL];

// ============================ helpers ============================
__device__ __forceinline__ void mma_f16(float* c,
    unsigned a0, unsigned a1, unsigned a2, unsigned a3,
    unsigned b0, unsigned b1)
{
    asm volatile(
        "mma.sync.aligned.m16n8k16.row.col.f32.f16.f16.f32 "
        "{%0,%1,%2,%3}, {%4,%5,%6,%7}, {%8,%9}, {%0,%1,%2,%3};"
        : "+f"(c[0]), "+f"(c[1]), "+f"(c[2]), "+f"(c[3])
        : "r"(a0), "r"(a1), "r"(a2), "r"(a3), "r"(b0), "r"(b1));
}

__device__ __forceinline__ void ldsm4(unsigned* r, unsigned addr) {
    asm volatile(
        "ldmatrix.sync.aligned.m8n8.x4.shared.b16 {%0,%1,%2,%3}, [%4];"
        : "=r"(r[0]), "=r"(r[1]), "=r"(r[2]), "=r"(r[3]) : "r"(addr));
}
__device__ __forceinline__ void ldsm4t(unsigned* r, unsigned addr) {
    asm volatile(
        "ldmatrix.sync.aligned.m8n8.x4.trans.shared.b16 {%0,%1,%2,%3}, [%4];"
        : "=r"(r[0]), "=r"(r[1]), "=r"(r[2]), "=r"(r[3]) : "r"(addr));
}

__device__ __forceinline__ void cp16(void* dst_sh, const void* src) {
    unsigned sa = (unsigned)__cvta_generic_to_shared(dst_sh);
    asm volatile("cp.async.cg.shared.global [%0], [%1], 16;" :: "r"(sa), "l"(src));
}
__device__ __forceinline__ void cp_commit() {
    asm volatile("cp.async.commit_group;");
}
template <int N>
__device__ __forceinline__ void cp_wait() {
    asm volatile("cp.async.wait_group %0;" :: "n"(N));
}

__device__ __forceinline__ float gelu_exact(float v) {
    return 0.5f * v * (1.0f + erff(v * 0.70710678118654752f));
}

__device__ __forceinline__ unsigned h2u(__half2 h) {
    unsigned u;
    *(__half2*)&u = h;
    return u;
}

// ============================ fp32 -> fp16 convert ============================
__global__ void __launch_bounds__(256) to_half_kernel(
    const float4* __restrict__ src, uint4* __restrict__ dst, int n8)
{
    int i = blockIdx.x * 256 + threadIdx.x;
    if (i < n8) {
        float4 v0 = src[2 * i], v1 = src[2 * i + 1];
        uint4 o;
        o.x = h2u(__floats2half2_rn(v0.x, v0.y));
        o.y = h2u(__floats2half2_rn(v0.z, v0.w));
        o.z = h2u(__floats2half2_rn(v1.x, v1.y));
        o.w = h2u(__floats2half2_rn(v1.z, v1.w));
        dst[i] = o;
    }
}

// ============================ LayerNorm (half output) ============================
__global__ void __launch_bounds__(256) ln_kernel(
    const float* __restrict__ x, const float* __restrict__ g,
    const float* __restrict__ b, __half* __restrict__ out)
{
    __shared__ float red[2][8];
    int row = blockIdx.x, tid = threadIdx.x;
    const float4* xr = (const float4*)(x + (size_t)row * D_MODEL);
    float4 v0 = xr[tid];
    float4 v1 = xr[tid + 256];
    float s  = v0.x + v0.y + v0.z + v0.w + v1.x + v1.y + v1.z + v1.w;
    float s2 = v0.x*v0.x + v0.y*v0.y + v0.z*v0.z + v0.w*v0.w
             + v1.x*v1.x + v1.y*v1.y + v1.z*v1.z + v1.w*v1.w;
    #pragma unroll
    for (int o = 16; o; o >>= 1) {
        s  += __shfl_xor_sync(0xffffffffu, s,  o);
        s2 += __shfl_xor_sync(0xffffffffu, s2, o);
    }
    if ((tid & 31) == 0) { red[0][tid >> 5] = s; red[1][tid >> 5] = s2; }
    __syncthreads();
    if (tid < 32) {
        float a = (tid < 8) ? red[0][tid] : 0.f;
        float c = (tid < 8) ? red[1][tid] : 0.f;
        #pragma unroll
        for (int o = 4; o; o >>= 1) {
            a += __shfl_xor_sync(0xffffffffu, a, o);
            c += __shfl_xor_sync(0xffffffffu, c, o);
        }
        if (tid == 0) { red[0][0] = a; red[1][0] = c; }
    }
    __syncthreads();
    float mean = red[0][0] * (1.f / D_MODEL);
    float var  = red[1][0] * (1.f / D_MODEL) - mean * mean;
    float rstd = rsqrtf(var + 1e-5f);

    const float4* gr = (const float4*)g;
    const float4* br = (const float4*)b;
    __half2* orow = (__half2*)(out + (size_t)row * D_MODEL);
    #pragma unroll
    for (int p = 0; p < 2; p++) {
        float4 v = p ? v1 : v0;
        float4 gw = gr[tid + p * 256];
        float4 bw = br[tid + p * 256];
        orow[2 * (tid + p * 256) + 0] = __floats2half2_rn(
            (v.x - mean) * rstd * gw.x + bw.x,
            (v.y - mean) * rstd * gw.y + bw.y);
        orow[2 * (tid + p * 256) + 1] = __floats2half2_rn(
            (v.z - mean) * rstd * gw.z + bw.z,
            (v.w - mean) * rstd * gw.w + bw.w);
    }
}

// ============================ fp16 mma GEMM: cp.async 3-stage + ldmatrix ============================
// EPI: 0 = bias -> half; 1 = bias + fp32 residual -> fp32; 2 = bias + GELU -> half
// Single barrier per ktile: wait<1> -> BAR -> prefetch(kb+2) -> compute(kb).
// The top BAR both publishes stage kb and protects restage of (kb+2)%3
// (last read at iter kb-1).
#define GBM 128
#define GBN 128
#define GBK 64
#define TILE_H (128 * 64)
#define NSTAGE 3
#define STAGE_H (2 * TILE_H)
#define GEMM_SMEM (NSTAGE * STAGE_H * 2)  // 98304 B

template <int EPI>
__global__ void __launch_bounds__(256, 2) gemm_kernel(
    const __half* __restrict__ A, const __half* __restrict__ B,
    const float* __restrict__ bias, const float* __restrict__ res,
    void* __restrict__ Cv, int M, int N, int K)
{
    extern __shared__ __half smh[];
    int tid = threadIdx.x;
    int bm = blockIdx.y, bn = blockIdx.x;
    int warp = tid >> 5, lane = tid & 31;
    int wm = warp >> 1, wn = warp & 1;
    int g = lane >> 2, c = lane & 3;

    int srow0 = tid >> 3, sc8 = tid & 7;
    const __half* Asrc0 = A + (size_t)(bm * GBM + srow0) * K + sc8 * 8;
    const __half* Bsrc0 = B + (size_t)(bn * GBN + srow0) * K + sc8 * 8;
    int sdst0 = srow0 * 64 + ((sc8 ^ (srow0 & 7)) << 3);

    float acc[2][8][4];
    #pragma unroll
    for (int mt = 0; mt < 2; mt++)
        #pragma unroll
        for (int nt = 0; nt < 8; nt++)
            #pragma unroll
            for (int q = 0; q < 4; q++) acc[mt][nt][q] = 0.f;

    int kt = K / GBK;

    unsigned smbase = (unsigned)__cvta_generic_to_shared(smh);
    int l7 = lane & 7;
    int arow = wm * 32 + l7 + ((lane >> 3) & 1) * 8;
    int brow = wn * 64 + l7 + (lane >> 4) * 8;
    unsigned abyte0 = smbase + arow * 128;
    unsigned bbyte0 = smbase + TILE_H * 2 + brow * 128;
    int kA = lane >> 4;
    int kB = (lane >> 3) & 1;

    // prologue: stage ktiles 0,1 (two commit groups)
    #pragma unroll
    for (int s = 0; s < NSTAGE - 1; s++) {
        #pragma unroll
        for (int p = 0; p < 4; p++) {
            cp16(smh + s * STAGE_H + sdst0 + p * 2048,
                 Asrc0 + (size_t)(32 * p) * K + s * GBK);
            cp16(smh + s * STAGE_H + TILE_H + sdst0 + p * 2048,
                 Bsrc0 + (size_t)(32 * p) * K + s * GBK);
        }
        cp_commit();
    }

    for (int kb = 0; kb < kt; ++kb) {
        int cur = kb % NSTAGE;
        // group kb (issued at iter kb-2 or prologue) must be done
        if (kb < kt - 1) cp_wait<1>(); else cp_wait<0>();
        __syncthreads();   // publish stage kb; all warps done reading (kb+2)%3

        if (kb + 2 < kt) {
            int nst = (kb + 2) % NSTAGE;
            #pragma unroll
            for (int p = 0; p < 4; p++) {
                cp16(smh + nst * STAGE_H + sdst0 + p * 2048,
                     Asrc0 + (size_t)(32 * p) * K + (kb + 2) * GBK);
                cp16(smh + nst * STAGE_H + TILE_H + sdst0 + p * 2048,
                     Bsrc0 + (size_t)(32 * p) * K + (kb + 2) * GBK);
            }
            cp_commit();
        }

        unsigned aB = abyte0 + cur * (STAGE_H * 2);
        unsigned bB = bbyte0 + cur * (STAGE_H * 2);

        #pragma unroll
        for (int kc = 0; kc < 4; kc++) {
            unsigned fa[2][4];
            #pragma unroll
            for (int mt = 0; mt < 2; mt++)
                ldsm4(fa[mt], aB + mt * (16 * 128) + ((unsigned)((2 * kc + kA) ^ l7) << 4));
            unsigned fb[4][4];
            #pragma unroll
            for (int p = 0; p < 4; p++)
                ldsm4(fb[p], bB + p * (16 * 128) + ((unsigned)((2 * kc + kB) ^ l7) << 4));
            #pragma unroll
            for (int mt = 0; mt < 2; mt++)
                #pragma unroll
                for (int nt = 0; nt < 8; nt++)
                    mma_f16(acc[mt][nt],
                            fa[mt][0], fa[mt][1], fa[mt][2], fa[mt][3],
                            fb[nt >> 1][(nt & 1) * 2], fb[nt >> 1][(nt & 1) * 2 + 1]);
        }
    }

    int row0g = bm * GBM + wm * 32;
    int col0g = bn * GBN + wn * 64;
    #pragma unroll
    for (int mt = 0; mt < 2; mt++)
        #pragma unroll
        for (int nt = 0; nt < 8; nt++)
            #pragma unroll
            for (int h2 = 0; h2 < 2; h2++) {
                int row = row0g + mt * 16 + h2 * 8 + g;
                int col = col0g + nt * 8 + 2 * c;
                float vx = acc[mt][nt][2 * h2 + 0] + bias[col];
                float vy = acc[mt][nt][2 * h2 + 1] + bias[col + 1];
                size_t off = (size_t)row * N + col;
                if (EPI == 0) {
                    __half* Ch = (__half*)Cv;
                    *(__half2*)(Ch + off) = __floats2half2_rn(vx, vy);
                } else if (EPI == 2) {
                    __half* Ch = (__half*)Cv;
                    *(__half2*)(Ch + off) =
                        __floats2half2_rn(gelu_exact(vx), gelu_exact(vy));
                } else {
                    float* Cf = (float*)Cv;
                    float2 r = *(const float2*)(res + off);
                    vx += r.x; vy += r.y;
                    *(float2*)(Cf + off) = make_float2(vx, vy);
                }
            }
}

// ============================ fp16 tensor-core flash attention ============================
// CTA: 128 q x 64-key tiles, 8 warps (16 q-rows each). Double-buffered K/V
// (cp.async prefetch of tile jt+1 overlaps compute of jt; single barrier/tile).
// Heavy-first scheduling: qi reversed so long blocks launch first.
#define QS_OFF 0                       // 2 t x 128x64 halfs (32 KB)
#define KS_OFF (2 * 128 * 64)          // 2 buf x 2 t x 64x64 (32 KB)
#define VS_OFF (KS_OFF + 2 * 2 * 64 * 64)
#define PS_OFF (VS_OFF + 2 * 2 * 64 * 64)  // 8 warps x 16x64 (16 KB)
#define ATT_HALFS (PS_OFF + 8 * 16 * 64)
#define ATT_SMEM (ATT_HALFS * 2)       // 114688 B
#define NEG_BIG (-1e30f)

__global__ void __launch_bounds__(256, 1) attn_kernel(
    const __half* __restrict__ qkv, const float* __restrict__ slopes,
    __half* __restrict__ out)
{
    extern __shared__ __half smA[];
    int qi = (int)gridDim.x - 1 - (int)blockIdx.x;   // heavy blocks first
    int h = blockIdx.y, b = blockIdx.z;
    int tid = threadIdx.x, warp = tid >> 5, lane = tid & 31;
    int g = lane >> 2, c = lane & 3, l7 = lane & 7;
    int q0 = qi * 128;
    float slope = slopes[h];
    const float scale = 0.08838834764831845f;   // 1/sqrt(128)

    const __half* qb = qkv + (size_t)(b * SEQ) * QKV_N + h * HD;
    const __half* kb = qb + D_MODEL;
    const __half* vb = qb + 2 * D_MODEL;

    unsigned smbase = (unsigned)__cvta_generic_to_shared(smA);
    __half* Pw = smA + PS_OFF + warp * 1024;
    unsigned pbase = smbase + (PS_OFF + warp * 1024) * 2;

    // stage Q (resident): 128 rows x 16 chunks of 16B  (commit group 0)
    for (int i = tid; i < 2048; i += 256) {
        int row = i >> 4, cc = i & 15;
        int t = cc >> 3, cw = cc & 7;
        cp16(smA + QS_OFF + t * 8192 + row * 64 + ((cw ^ (row & 7)) << 3),
             qb + (size_t)(q0 + row) * QKV_N + cc * 8);
    }
    cp_commit();

    // stage K/V tile 0 into buffer 0 (commit group 1)
    for (int i = tid; i < 1024; i += 256) {
        int row = i >> 4, cc = i & 15;
        int t = cc >> 3, cw = cc & 7;
        int d = row * 64 + ((cw ^ (row & 7)) << 3);
        cp16(smA + KS_OFF + t * 4096 + d, kb + (size_t)row * QKV_N + cc * 8);
        cp16(smA + VS_OFF + t * 4096 + d, vb + (size_t)row * QKV_N + cc * 8);
    }
    cp_commit();

    float m0 = NEG_BIG, m1 = NEG_BIG, l0 = 0.f, l1 = 0.f;
    float oc[16][4];
    #pragma unroll
    for (int nt = 0; nt < 16; nt++)
        #pragma unroll
        for (int q = 0; q < 4; q++) oc[nt][q] = 0.f;

    int rowA = 16 * warp + g;
    int qr0 = q0 + rowA, qr1 = qr0 + 8;

    // ldmatrix lane geometry
    int a_roff = ((lane >> 3) & 1) * 8 + l7;
    int a_csel = lane >> 4;
    int b_roff = (lane >> 4) * 8 + l7;
    int b_csel = (lane >> 3) & 1;
    int v_roff = ((lane >> 3) & 1) * 8 + l7;
    int v_csel = lane >> 4;

    int ntiles = 2 * qi + 2;
    for (int jt = 0; jt < ntiles; jt++) {
        int bsel = jt & 1;
        cp_wait<0>();      // group jt (and Q on first iter) complete
        __syncthreads();   // publish; all warps done reading buffer (jt+1)&1

        // prefetch K/V tile jt+1 into the other buffer (overlaps compute)
        if (jt + 1 < ntiles) {
            int j1 = (jt + 1) * 64;
            int ns = bsel ^ 1;
            for (int i = tid; i < 1024; i += 256) {
                int row = i >> 4, cc = i & 15;
                int t = cc >> 3, cw = cc & 7;
                int d = row * 64 + ((cw ^ (row & 7)) << 3);
                cp16(smA + KS_OFF + ns * 8192 + t * 4096 + d,
                     kb + (size_t)(j1 + row) * QKV_N + cc * 8);
                cp16(smA + VS_OFF + ns * 8192 + t * 4096 + d,
                     vb + (size_t)(j1 + row) * QKV_N + cc * 8);
            }
            cp_commit();
        }

        int j0 = jt * 64;
        unsigned kbb = smbase + (KS_OFF + bsel * 8192) * 2;
        unsigned vbb = smbase + (VS_OFF + bsel * 8192) * 2;

        // ---- S = Q K^T ----
        float sc[8][4];
        #pragma unroll
        for (int nt = 0; nt < 8; nt++)
            #pragma unroll
            for (int q = 0; q < 4; q++) sc[nt][q] = 0.f;

        #pragma unroll
        for (int kc = 0; kc < 8; kc++) {
            int t = kc >> 2, k2 = kc & 3;
            unsigned fa[4];
            {
                int row = warp * 16 + a_roff;
                unsigned addr = smbase +
                    (QS_OFF + t * 8192 + row * 64 + (((k2 * 2 + a_csel) ^ l7) << 3)) * 2;
                ldsm4(fa, addr);
            }
            unsigned fb[4][4];
            #pragma unroll
            for (int p = 0; p < 4; p++) {
                int key = 16 * p + b_roff;
                unsigned addr = kbb +
                    (t * 4096 + key * 64 + (((k2 * 2 + b_csel) ^ l7) << 3)) * 2;
                ldsm4(fb[p], addr);
            }
            #pragma unroll
            for (int nt = 0; nt < 8; nt++)
                mma_f16(sc[nt], fa[0], fa[1], fa[2], fa[3],
                        fb[nt >> 1][(nt & 1) * 2], fb[nt >> 1][(nt & 1) * 2 + 1]);
        }

        // ---- scale + ALiBi + causal + online softmax (fp32) ----
        bool masked = (jt >= 2 * qi);
        float tm0 = NEG_BIG, tm1 = NEG_BIG;
        #pragma unroll
        for (int nt = 0; nt < 8; nt++) {
            #pragma unroll
            for (int j = 0; j < 2; j++) {
                int col = j0 + nt * 8 + 2 * c + j;
                float s0 = sc[nt][j]     * scale + slope * (float)(col - qr0);
                float s1 = sc[nt][2 + j] * scale + slope * (float)(col - qr1);
                if (masked) {
                    if (col > qr0) s0 = NEG_BIG;
                    if (col > qr1) s1 = NEG_BIG;
                }
                sc[nt][j] = s0; sc[nt][2 + j] = s1;
                tm0 = fmaxf(tm0, s0); tm1 = fmaxf(tm1, s1);
            }
        }
        #pragma unroll
        for (int o = 1; o < 4; o <<= 1) {
            tm0 = fmaxf(tm0, __shfl_xor_sync(0xffffffffu, tm0, o));
            tm1 = fmaxf(tm1, __shfl_xor_sync(0xffffffffu, tm1, o));
        }
        float mn0 = fmaxf(m0, tm0), mn1 = fmaxf(m1, tm1);
        float alpha0 = __expf(m0 - mn0), alpha1 = __expf(m1 - mn1);
        float rs0 = 0.f, rs1 = 0.f;
        #pragma unroll
        for (int nt = 0; nt < 8; nt++) {
            #pragma unroll
            for (int j = 0; j < 2; j++) {
                float p0 = __expf(sc[nt][j]     - mn0);
                float p1 = __expf(sc[nt][2 + j] - mn1);
                sc[nt][j] = p0; sc[nt][2 + j] = p1;
                rs0 += p0; rs1 += p1;
            }
        }
        #pragma unroll
        for (int o = 1; o < 4; o <<= 1) {
            rs0 += __shfl_xor_sync(0xffffffffu, rs0, o);
            rs1 += __shfl_xor_sync(0xffffffffu, rs1, o);
        }
        l0 = l0 * alpha0 + rs0;
        l1 = l1 * alpha1 + rs1;
        m0 = mn0; m1 = mn1;
        #pragma unroll
        for (int nt = 0; nt < 16; nt++) {
            oc[nt][0] *= alpha0; oc[nt][1] *= alpha0;
            oc[nt][2] *= alpha1; oc[nt][3] *= alpha1;
        }

        // ---- stage P (half, swizzled 16x64 per warp) ----
        __syncwarp();
        #pragma unroll
        for (int nt = 0; nt < 8; nt++) {
            *(__half2*)(Pw + g * 64 + ((nt ^ (g & 7)) << 3) + 2 * c) =
                __floats2half2_rn(sc[nt][0], sc[nt][1]);
            *(__half2*)(Pw + (g + 8) * 64 + ((nt ^ (g & 7)) << 3) + 2 * c) =
                __floats2half2_rn(sc[nt][2], sc[nt][3]);
        }
        __syncwarp();

        // ---- O += P @ V ----
        #pragma unroll
        for (int kc2 = 0; kc2 < 4; kc2++) {
            unsigned fa[4];
            {
                unsigned addr = pbase +
                    (a_roff * 64 + (((kc2 * 2 + a_csel) ^ l7) << 3)) * 2;
                ldsm4(fa, addr);
            }
            unsigned fv[8][4];
            #pragma unroll
            for (int nv = 0; nv < 8; nv++) {
                int t = nv >> 2;
                int cw = (nv & 3) * 2 + v_csel;
                int key = kc2 * 16 + v_roff;
                unsigned addr = vbb +
                    (t * 4096 + key * 64 + ((cw ^ l7) << 3)) * 2;
                ldsm4t(fv[nv], addr);
            }
            #pragma unroll
            for (int nt = 0; nt < 16; nt++)
                mma_f16(oc[nt], fa[0], fa[1], fa[2], fa[3],
                        fv[nt >> 1][(nt & 1) * 2], fv[nt >> 1][(nt & 1) * 2 + 1]);
        }
    }

    // ---- normalize + write half ----
    float inv0 = 1.f / l0, inv1 = 1.f / l1;
    __half* ob  = out + (size_t)(b * SEQ + qr0) * D_MODEL + h * HD;
    __half* ob1 = ob + 8 * D_MODEL;
    #pragma unroll
    for (int nt = 0; nt < 16; nt++) {
        *(__half2*)&ob[nt * 8 + 2 * c] =
            __floats2half2_rn(oc[nt][0] * inv0, oc[nt][1] * inv0);
        *(__half2*)&ob1[nt * 8 + 2 * c] =
            __floats2half2_rn(oc[nt][2] * inv1, oc[nt][3] * inv1);
    }
}

// ============================ launch ============================
extern "C" void kernel_launch(void* const* d_in, const int* in_sizes, int n_in,
                              void* d_out, int out_size)
{
    const float* x      = (const float*)d_in[0];
    const float* ln1_w  = (const float*)d_in[1];
    const float* ln1_b  = (const float*)d_in[2];
    const float* Wqkv   = (const float*)d_in[3];
    const float* bqkv   = (const float*)d_in[4];
    const float* Wo     = (const float*)d_in[5];
    const float* bo     = (const float*)d_in[6];
    const float* ln2_w  = (const float*)d_in[7];
    const float* ln2_b  = (const float*)d_in[8];
    const float* W1     = (const float*)d_in[9];
    const float* b1     = (const float*)d_in[10];
    const float* W2     = (const float*)d_in[11];
    const float* b2     = (const float*)d_in[12];
    const float* slopes = (const float*)d_in[13];
    float* out = (float*)d_out;

    __half *h, *qkv, *attn, *mlp, *wh;
    cudaGetSymbolAddress((void**)&h,    g_h);
    cudaGetSymbolAddress((void**)&qkv,  g_qkv);
    cudaGetSymbolAddress((void**)&attn, g_attn);
    cudaGetSymbolAddress((void**)&mlp,  g_mlp);
    cudaGetSymbolAddress((void**)&wh,   g_wh);

    cudaFuncSetAttribute(attn_kernel,
                         cudaFuncAttributeMaxDynamicSharedMemorySize, ATT_SMEM);
    cudaFuncSetAttribute(gemm_kernel<0>,
                         cudaFuncAttributeMaxDynamicSharedMemorySize, GEMM_SMEM);
    cudaFuncSetAttribute(gemm_kernel<1>,
                         cudaFuncAttributeMaxDynamicSharedMemorySize, GEMM_SMEM);
    cudaFuncSetAttribute(gemm_kernel<2>,
                         cudaFuncAttributeMaxDynamicSharedMemorySize, GEMM_SMEM);

    // 0. convert weights to half
    {
        int n8;
        n8 = 3 * D_MODEL * D_MODEL / 8;
        to_half_kernel<<<(n8 + 255) / 256, 256>>>((const float4*)Wqkv,
            (uint4*)(wh + WQKV_OFF), n8);
        n8 = D_MODEL * D_MODEL / 8;
        to_half_kernel<<<(n8 + 255) / 256, 256>>>((const float4*)Wo,
            (uint4*)(wh + WO_OFF), n8);
        n8 = D_FF * D_MODEL / 8;
        to_half_kernel<<<(n8 + 255) / 256, 256>>>((const float4*)W1,
            (uint4*)(wh + W1_OFF), n8);
        n8 = D_MODEL * D_FF / 8;
        to_half_kernel<<<(n8 + 255) / 256, 256>>>((const float4*)W2,
            (uint4*)(wh + W2_OFF), n8);
    }

    // 1. LN1 -> half
    ln_kernel<<<ROWS, 256>>>(x, ln1_w, ln1_b, h);
    // 2. QKV GEMM -> half
    gemm_kernel<0><<<dim3(QKV_N / GBN, ROWS / GBM), 256, GEMM_SMEM>>>(
        h, wh + WQKV_OFF, bqkv, nullptr, qkv, ROWS, QKV_N, D_MODEL);
    // 3. Flash attention with ALiBi (fp16 mma) -> half
    attn_kernel<<<dim3(SEQ / 128, NH, BATCH), 256, ATT_SMEM>>>(qkv, slopes, attn);
    // 4. O projection + residual (x) -> d_out fp32
    gemm_kernel<1><<<dim3(D_MODEL / GBN, ROWS / GBM), 256, GEMM_SMEM>>>(
        attn, wh + WO_OFF, bo, x, out, ROWS, D_MODEL, D_MODEL);
    // 5. LN2 -> half
    ln_kernel<<<ROWS, 256>>>(out, ln2_w, ln2_b, h);
    // 6. MLP up + GELU -> half
    gemm_kernel<2><<<dim3(D_FF / GBN, ROWS / GBM), 256, GEMM_SMEM>>>(
        h, wh + W1_OFF, b1, nullptr, mlp, ROWS, D_FF, D_MODEL);
    // 7. MLP down + residual (x1 in d_out) -> d_out fp32 final
    gemm_kernel<1><<<dim3(D_MODEL / GBN, ROWS / GBM), 256, GEMM_SMEM>>>(
        mlp, wh + W2_OFF, b2, out, out, ROWS, D_MODEL, D_FF);
}